// round 4
// baseline (speedup 1.0000x reference)
#include <cuda_runtime.h>
#include <cuda_bf16.h>
#include <cstdint>
#include <cstddef>

// Problem constants
#define BATCH 8
#define CC    512
#define LL    2048
#define NGROUPS 32
#define CPG   (CC / NGROUPS)      // 16
#define GROUP_ELEMS (CPG * LL)    // 32768
#define EPS   1e-5f

// ---------------------------------------------------------------------------
// Device scratch
// ---------------------------------------------------------------------------
__device__ float g_h[(size_t)BATCH * CC * LL];
__device__ float g_q[(size_t)BATCH * CC * LL];
__device__ float g_k[(size_t)BATCH * CC * LL];
__device__ float g_v[(size_t)BATCH * CC * LL];
__device__ float g_w[(size_t)BATCH * LL * LL];
__device__ float g_a[(size_t)BATCH * CC * LL];

// ---------------------------------------------------------------------------
// Helpers
// ---------------------------------------------------------------------------
__device__ __forceinline__ float warp_sum(float v) {
    #pragma unroll
    for (int o = 16; o > 0; o >>= 1) v += __shfl_xor_sync(0xffffffffu, v, o);
    return v;
}
__device__ __forceinline__ float warp_max(float v) {
    #pragma unroll
    for (int o = 16; o > 0; o >>= 1) v = fmaxf(v, __shfl_xor_sync(0xffffffffu, v, o));
    return v;
}
__device__ __forceinline__ float to_tf32(float x) {
    float r;
    asm("cvt.rna.tf32.f32 %0, %1;" : "=f"(r) : "f"(x));
    return r;
}
__device__ __forceinline__ void mma8(float* d, const uint32_t* a, const uint32_t* b) {
    asm volatile(
        "mma.sync.aligned.m16n8k8.row.col.f32.tf32.tf32.f32 "
        "{%0,%1,%2,%3}, {%4,%5,%6,%7}, {%8,%9}, {%0,%1,%2,%3};\n"
        : "+f"(d[0]), "+f"(d[1]), "+f"(d[2]), "+f"(d[3])
        : "r"(a[0]), "r"(a[1]), "r"(a[2]), "r"(a[3]), "r"(b[0]), "r"(b[1]));
}

// ---------------------------------------------------------------------------
// GroupNorm (unchanged)
// ---------------------------------------------------------------------------
__global__ void gn_kernel(const float* __restrict__ x,
                          const float* __restrict__ gamma,
                          const float* __restrict__ beta,
                          float* __restrict__ h) {
    const int bg = blockIdx.x;
    const int b  = bg / NGROUPS;
    const int g  = bg % NGROUPS;
    const size_t base = ((size_t)b * CC + (size_t)g * CPG) * LL;
    const float* xp = x + base;

    float s = 0.f, s2 = 0.f;
    for (int i = threadIdx.x; i < GROUP_ELEMS; i += blockDim.x) {
        float v = xp[i];
        s += v; s2 += v * v;
    }
    __shared__ float red1[16], red2[16];
    s = warp_sum(s); s2 = warp_sum(s2);
    const int lane = threadIdx.x & 31, wid = threadIdx.x >> 5;
    if (lane == 0) { red1[wid] = s; red2[wid] = s2; }
    __syncthreads();
    if (wid == 0) {
        s  = (lane < 16) ? red1[lane] : 0.f;
        s2 = (lane < 16) ? red2[lane] : 0.f;
        s = warp_sum(s); s2 = warp_sum(s2);
        if (lane == 0) { red1[0] = s; red2[0] = s2; }
    }
    __syncthreads();
    const float mean = red1[0] * (1.0f / GROUP_ELEMS);
    const float var  = red2[0] * (1.0f / GROUP_ELEMS) - mean * mean;
    const float inv  = rsqrtf(var + EPS);

    float* hp = h + base;
    for (int i = threadIdx.x; i < GROUP_ELEMS; i += blockDim.x) {
        int c = g * CPG + i / LL;
        hp[i] = (xp[i] - mean) * inv * gamma[c] + beta[c];
    }
}

// ---------------------------------------------------------------------------
// Unified tf32 tensor-core GEMM.
//   out[b, m, n] = sum_k Aop[m,k] * Bop[n,k]   (+ epilogue)
// A_KMAJ: gmem A element (m,k) at A[k*lda + m]  (else A[m*lda + k])
// B_KMAJ: gmem B element (n,k) at B[k*ldb + n]  (else B[n*ldb + k])
// EPI: 0 plain, 1 +bias[m], 2 +bias[m]+X, 3 *scale
//
// Tile 128x128 x BK=32.  8 warps as 2(M) x 4(N); warp tile 64x32 = 4x4 m16n8k8.
// ---------------------------------------------------------------------------
#define BKK 32
#define KM_PAD 136   // 128 + 8 : fragment reads bank-conflict-free
#define MK_PAD 36    // 32 + 4

template<int EPI, bool A_KMAJ, bool B_KMAJ>
__global__ __launch_bounds__(256, 2)
void mma_gemm(const float* __restrict__ A, int lda, size_t sA,
              const float* __restrict__ B, int ldb, size_t sB,
              float* __restrict__ O, int ldo, size_t sO,
              int K,
              const float* __restrict__ bias,
              const float* __restrict__ X, size_t sX,
              float scale) {
    constexpr int ASZ = A_KMAJ ? BKK * KM_PAD : 128 * MK_PAD;
    constexpr int BSZ = B_KMAJ ? BKK * KM_PAD : 128 * MK_PAD;
    __shared__ float sAm[ASZ];
    __shared__ float sBm[BSZ];

    const int tid  = threadIdx.x;
    const int warp = tid >> 5, lane = tid & 31;
    const int wm = warp >> 2;        // 0..1
    const int wn = warp & 3;         // 0..3
    const int g  = lane >> 2;        // 0..7
    const int tig = lane & 3;        // 0..3
    const int mBase = blockIdx.y * 128;
    const int nBase = blockIdx.x * 128;

    const float* Ab = A + (size_t)blockIdx.z * sA;
    const float* Bb = B + (size_t)blockIdx.z * sB;

    float acc[4][4][4];
    #pragma unroll
    for (int i = 0; i < 4; i++)
        #pragma unroll
        for (int j = 0; j < 4; j++)
            #pragma unroll
            for (int r = 0; r < 4; r++) acc[i][j][r] = 0.f;

    for (int k0 = 0; k0 < K; k0 += BKK) {
        // ---- load + convert A tile ----
        if (A_KMAJ) {
            #pragma unroll
            for (int it = 0; it < 4; it++) {
                int s = tid + it * 256;
                int kk = s >> 5, mv = (s & 31) * 4;
                float4 t = *(const float4*)(Ab + (size_t)(k0 + kk) * lda + mBase + mv);
                float4 c = { to_tf32(t.x), to_tf32(t.y), to_tf32(t.z), to_tf32(t.w) };
                *(float4*)(sAm + kk * KM_PAD + mv) = c;
            }
        } else {
            #pragma unroll
            for (int it = 0; it < 4; it++) {
                int s = tid + it * 256;
                int m = s >> 3, kv = (s & 7) * 4;
                float4 t = *(const float4*)(Ab + (size_t)(mBase + m) * lda + k0 + kv);
                float4 c = { to_tf32(t.x), to_tf32(t.y), to_tf32(t.z), to_tf32(t.w) };
                *(float4*)(sAm + m * MK_PAD + kv) = c;
            }
        }
        // ---- load + convert B tile ----
        if (B_KMAJ) {
            #pragma unroll
            for (int it = 0; it < 4; it++) {
                int s = tid + it * 256;
                int kk = s >> 5, nv = (s & 31) * 4;
                float4 t = *(const float4*)(Bb + (size_t)(k0 + kk) * ldb + nBase + nv);
                float4 c = { to_tf32(t.x), to_tf32(t.y), to_tf32(t.z), to_tf32(t.w) };
                *(float4*)(sBm + kk * KM_PAD + nv) = c;
            }
        } else {
            #pragma unroll
            for (int it = 0; it < 4; it++) {
                int s = tid + it * 256;
                int n = s >> 3, kv = (s & 7) * 4;
                float4 t = *(const float4*)(Bb + (size_t)(nBase + n) * ldb + k0 + kv);
                float4 c = { to_tf32(t.x), to_tf32(t.y), to_tf32(t.z), to_tf32(t.w) };
                *(float4*)(sBm + n * MK_PAD + kv) = c;
            }
        }
        __syncthreads();

        #pragma unroll
        for (int ks = 0; ks < BKK / 8; ks++) {
            const int kb = ks * 8;
            uint32_t af[4][4], bf[4][2];
            #pragma unroll
            for (int mt = 0; mt < 4; mt++) {
                const int r0 = wm * 64 + mt * 16 + g;
                if (A_KMAJ) {
                    af[mt][0] = __float_as_uint(sAm[(kb + tig) * KM_PAD + r0]);
                    af[mt][1] = __float_as_uint(sAm[(kb + tig) * KM_PAD + r0 + 8]);
                    af[mt][2] = __float_as_uint(sAm[(kb + tig + 4) * KM_PAD + r0]);
                    af[mt][3] = __float_as_uint(sAm[(kb + tig + 4) * KM_PAD + r0 + 8]);
                } else {
                    af[mt][0] = __float_as_uint(sAm[r0 * MK_PAD + kb + tig]);
                    af[mt][1] = __float_as_uint(sAm[(r0 + 8) * MK_PAD + kb + tig]);
                    af[mt][2] = __float_as_uint(sAm[r0 * MK_PAD + kb + tig + 4]);
                    af[mt][3] = __float_as_uint(sAm[(r0 + 8) * MK_PAD + kb + tig + 4]);
                }
            }
            #pragma unroll
            for (int nt = 0; nt < 4; nt++) {
                const int c0 = wn * 32 + nt * 8 + g;
                if (B_KMAJ) {
                    bf[nt][0] = __float_as_uint(sBm[(kb + tig) * KM_PAD + c0]);
                    bf[nt][1] = __float_as_uint(sBm[(kb + tig + 4) * KM_PAD + c0]);
                } else {
                    bf[nt][0] = __float_as_uint(sBm[c0 * MK_PAD + kb + tig]);
                    bf[nt][1] = __float_as_uint(sBm[c0 * MK_PAD + kb + tig + 4]);
                }
            }
            #pragma unroll
            for (int mt = 0; mt < 4; mt++)
                #pragma unroll
                for (int nt = 0; nt < 4; nt++)
                    mma8(acc[mt][nt], af[mt], bf[nt]);
        }
        __syncthreads();
    }

    // ---- epilogue ----
    float* Ob = O + (size_t)blockIdx.z * sO;
    const float* Xb = (EPI == 2) ? (X + (size_t)blockIdx.z * sX) : nullptr;
    #pragma unroll
    for (int mt = 0; mt < 4; mt++) {
        const int r0 = mBase + wm * 64 + mt * 16 + g;
        #pragma unroll
        for (int half = 0; half < 2; half++) {
            const int row = r0 + half * 8;
            float bv = 0.f;
            if (EPI == 1 || EPI == 2) bv = bias[row];
            #pragma unroll
            for (int nt = 0; nt < 4; nt++) {
                const int col = nBase + wn * 32 + nt * 8 + tig * 2;
                float v0 = acc[mt][nt][half * 2 + 0];
                float v1 = acc[mt][nt][half * 2 + 1];
                if (EPI == 3) { v0 *= scale; v1 *= scale; }
                if (EPI == 1 || EPI == 2) { v0 += bv; v1 += bv; }
                if (EPI == 2) {
                    const float* xr = Xb + (size_t)row * ldo + col;
                    v0 += xr[0]; v1 += xr[1];
                }
                float2 st = { v0, v1 };
                *(float2*)(Ob + (size_t)row * ldo + col) = st;
            }
        }
    }
}

// ---------------------------------------------------------------------------
// Softmax (unchanged)
// ---------------------------------------------------------------------------
__global__ void softmax_kernel(float* __restrict__ w) {
    float* p = w + (size_t)blockIdx.x * LL;
    __shared__ float red[8];
    const int lane = threadIdx.x & 31, wid = threadIdx.x >> 5;

    float m = -1e30f;
    for (int i = threadIdx.x; i < LL; i += 256) m = fmaxf(m, p[i]);
    m = warp_max(m);
    if (lane == 0) red[wid] = m;
    __syncthreads();
    if (wid == 0) {
        m = (lane < 8) ? red[lane] : -1e30f;
        m = warp_max(m);
        if (lane == 0) red[0] = m;
    }
    __syncthreads();
    m = red[0];
    __syncthreads();

    float s = 0.f;
    for (int i = threadIdx.x; i < LL; i += 256) {
        float e = __expf(p[i] - m);
        p[i] = e;
        s += e;
    }
    s = warp_sum(s);
    if (lane == 0) red[wid] = s;
    __syncthreads();
    if (wid == 0) {
        s = (lane < 8) ? red[lane] : 0.f;
        s = warp_sum(s);
        if (lane == 0) red[0] = s;
    }
    __syncthreads();
    const float inv = 1.0f / red[0];
    for (int i = threadIdx.x; i < LL; i += 256) p[i] *= inv;
}

// ---------------------------------------------------------------------------
// Launch
// ---------------------------------------------------------------------------
extern "C" void kernel_launch(void* const* d_in, const int* in_sizes, int n_in,
                              void* d_out, int out_size) {
    const float* x        = (const float*)d_in[0];
    const float* gn_gamma = (const float*)d_in[1];
    const float* gn_beta  = (const float*)d_in[2];
    const float* Wq = (const float*)d_in[3];
    const float* bq = (const float*)d_in[4];
    const float* Wk = (const float*)d_in[5];
    const float* bk = (const float*)d_in[6];
    const float* Wv = (const float*)d_in[7];
    const float* bv = (const float*)d_in[8];
    const float* Wo = (const float*)d_in[9];
    const float* bo = (const float*)d_in[10];
    float* out = (float*)d_out;

    float *h, *q, *k, *v, *w, *a;
    cudaGetSymbolAddress((void**)&h, g_h);
    cudaGetSymbolAddress((void**)&q, g_q);
    cudaGetSymbolAddress((void**)&k, g_k);
    cudaGetSymbolAddress((void**)&v, g_v);
    cudaGetSymbolAddress((void**)&w, g_w);
    cudaGetSymbolAddress((void**)&a, g_a);

    const size_t CL = (size_t)CC * LL;
    const size_t LLs = (size_t)LL * LL;
    const float scale = 0.044194173824159216f;   // 1/sqrt(512)

    // 1. GroupNorm
    gn_kernel<<<BATCH * NGROUPS, 512>>>(x, gn_gamma, gn_beta, h);

    // 2. q,k,v projections: M=C(512), N=L(2048), K=C. A=W (m-major), B=h (k-major)
    dim3 gproj(LL / 128, CC / 128, BATCH);
    mma_gemm<1, false, true><<<gproj, 256>>>(Wq, CC, 0, h, LL, CL, q, LL, CL,
                                             CC, bq, nullptr, 0, 0.f);
    mma_gemm<1, false, true><<<gproj, 256>>>(Wk, CC, 0, h, LL, CL, k, LL, CL,
                                             CC, bk, nullptr, 0, 0.f);
    mma_gemm<1, false, true><<<gproj, 256>>>(Wv, CC, 0, h, LL, CL, v, LL, CL,
                                             CC, bv, nullptr, 0, 0.f);

    // 3. scores: M=N=L, K=C. A=q (k-major), B=k (k-major), *scale
    dim3 gqk(LL / 128, LL / 128, BATCH);
    mma_gemm<3, true, true><<<gqk, 256>>>(q, LL, CL, k, LL, CL, w, LL, LLs,
                                          CC, nullptr, nullptr, 0, scale);

    // 4. softmax rows
    softmax_kernel<<<BATCH * LL, 256>>>(w);

    // 5. a = attn @ v: M=C, N=L(i), K=L(j). A=v (m-major), B=w (n-major)
    dim3 gav(LL / 128, CC / 128, BATCH);
    mma_gemm<0, false, false><<<gav, 256>>>(v, LL, CL, w, LL, LLs, a, LL, CL,
                                            LL, nullptr, nullptr, 0, 0.f);

    // 6. out = x + Wo@a + bo
    mma_gemm<2, false, true><<<gproj, 256>>>(Wo, CC, 0, a, LL, CL, out, LL, CL,
                                             CC, bo, x, CL, 0.f);
}

// round 5
// speedup vs baseline: 1.8059x; 1.8059x over previous
#include <cuda_runtime.h>
#include <cuda_bf16.h>
#include <cstdint>
#include <cstddef>

#define BATCH 8
#define CC    512
#define LL    2048
#define NGROUPS 32
#define CPG   (CC / NGROUPS)      // 16
#define GROUP_ELEMS (CPG * LL)    // 32768
#define EPS   1e-5f

// ---------------------------------------------------------------------------
// Device scratch.  All GEMM operands stored k-contiguous.
// ---------------------------------------------------------------------------
__device__ __nv_bfloat16 g_hT[(size_t)BATCH * LL * CC];   // [b][l][c]
__device__ __nv_bfloat16 g_qT[(size_t)BATCH * LL * CC];   // [b][l][c]
__device__ __nv_bfloat16 g_kT[(size_t)BATCH * LL * CC];   // [b][l][c]
__device__ __nv_bfloat16 g_v [(size_t)BATCH * CC * LL];   // [b][c][l]
__device__ __nv_bfloat16 g_aT[(size_t)BATCH * LL * CC];   // [b][l][c]
__device__ float         g_w [(size_t)BATCH * LL * LL];   // scores fp32
__device__ __nv_bfloat16 g_wb[(size_t)BATCH * LL * LL];   // softmax out bf16
__device__ float2        g_stats[BATCH * NGROUPS];        // {mean, inv}

// ---------------------------------------------------------------------------
// Helpers
// ---------------------------------------------------------------------------
__device__ __forceinline__ float warp_sum(float v) {
    #pragma unroll
    for (int o = 16; o > 0; o >>= 1) v += __shfl_xor_sync(0xffffffffu, v, o);
    return v;
}
__device__ __forceinline__ float warp_max(float v) {
    #pragma unroll
    for (int o = 16; o > 0; o >>= 1) v = fmaxf(v, __shfl_xor_sync(0xffffffffu, v, o));
    return v;
}
__device__ __forceinline__ void ldsm4(uint32_t* r, const void* p) {
    uint32_t a = (uint32_t)__cvta_generic_to_shared(p);
    asm volatile("ldmatrix.sync.aligned.m8n8.x4.shared.b16 {%0,%1,%2,%3}, [%4];"
                 : "=r"(r[0]), "=r"(r[1]), "=r"(r[2]), "=r"(r[3]) : "r"(a));
}
__device__ __forceinline__ void mma16(float* d, const uint32_t* a, const uint32_t* b) {
    asm volatile(
        "mma.sync.aligned.m16n8k16.row.col.f32.bf16.bf16.f32 "
        "{%0,%1,%2,%3}, {%4,%5,%6,%7}, {%8,%9}, {%0,%1,%2,%3};\n"
        : "+f"(d[0]), "+f"(d[1]), "+f"(d[2]), "+f"(d[3])
        : "r"(a[0]), "r"(a[1]), "r"(a[2]), "r"(a[3]), "r"(b[0]), "r"(b[1]));
}
__device__ __forceinline__ uint32_t packbf2(float x, float y) {
    __nv_bfloat162 t = __floats2bfloat162_rn(x, y);
    return *(uint32_t*)&t;
}
__device__ __forceinline__ uint4 pack8(float4 a, float4 b) {
    uint4 r;
    r.x = packbf2(a.x, a.y); r.y = packbf2(a.z, a.w);
    r.z = packbf2(b.x, b.y); r.w = packbf2(b.z, b.w);
    return r;
}

// ---------------------------------------------------------------------------
// GroupNorm pass 1: per-(batch,group) mean & inv-std
// ---------------------------------------------------------------------------
__global__ void gn_stats(const float* __restrict__ x, float2* __restrict__ stats) {
    const int bg = blockIdx.x;
    const int b  = bg / NGROUPS;
    const int g  = bg % NGROUPS;
    const size_t base = ((size_t)b * CC + (size_t)g * CPG) * LL;
    const float* xp = x + base;

    float s = 0.f, s2 = 0.f;
    for (int i = threadIdx.x; i < GROUP_ELEMS; i += blockDim.x) {
        float v = xp[i];
        s += v; s2 += v * v;
    }
    __shared__ float red1[16], red2[16];
    s = warp_sum(s); s2 = warp_sum(s2);
    const int lane = threadIdx.x & 31, wid = threadIdx.x >> 5;
    if (lane == 0) { red1[wid] = s; red2[wid] = s2; }
    __syncthreads();
    if (threadIdx.x == 0) {
        float t = 0.f, t2 = 0.f;
        #pragma unroll
        for (int i = 0; i < 16; i++) { t += red1[i]; t2 += red2[i]; }
        float mean = t * (1.0f / GROUP_ELEMS);
        float var  = t2 * (1.0f / GROUP_ELEMS) - mean * mean;
        stats[bg] = make_float2(mean, rsqrtf(var + EPS));
    }
}

// ---------------------------------------------------------------------------
// GroupNorm pass 2: normalize + transpose + bf16:  hT[b][l][c]
// grid (L/32, C/64, B), 256 threads
// ---------------------------------------------------------------------------
__global__ void gn_norm_t(const float* __restrict__ x,
                          const float2* __restrict__ stats,
                          const float* __restrict__ gamma,
                          const float* __restrict__ beta,
                          __nv_bfloat16* __restrict__ hT) {
    const int b = blockIdx.z;
    const int l0 = blockIdx.x * 32;
    const int c0 = blockIdx.y * 64;
    const int tx = threadIdx.x & 31, ty = threadIdx.x >> 5;
    __shared__ float tile[64][33];

    const float* xb = x + (size_t)b * CC * LL;
    #pragma unroll
    for (int i = 0; i < 8; i++) {
        int c = c0 + i * 8 + ty;
        float2 st = stats[b * NGROUPS + (c >> 4)];
        float gm = gamma[c], bt = beta[c];
        float xv = xb[(size_t)c * LL + l0 + tx];
        tile[c - c0][tx] = (xv - st.x) * st.y * gm + bt;
    }
    __syncthreads();
    __nv_bfloat16* ht = hT + (size_t)b * LL * CC;
    #pragma unroll
    for (int i = 0; i < 4; i++) {
        int l = i * 8 + ty;
        __nv_bfloat162 o;
        o.x = __float2bfloat16_rn(tile[tx * 2][l]);
        o.y = __float2bfloat16_rn(tile[tx * 2 + 1][l]);
        *(__nv_bfloat162*)(ht + (size_t)(l0 + l) * CC + c0 + tx * 2) = o;
    }
}

// ---------------------------------------------------------------------------
// bf16 tensor-core GEMM:  out[b,m,n] = sum_k A[m,k] * B[n,k]  (+ epilogue)
// All operands k-contiguous. A_F32/B_F32: gmem fp32, converted on load.
// EPI: 0 none, 1 +bias[m], 2 +bias[m]+X, 3 *scale, 4 +bias[n]
// Tile 128x128xBK32, 8 warps (2x4), warp 64x32, m16n8k16, double-buffered.
// ---------------------------------------------------------------------------
#define BKK 32
#define SROW 40   // 32 + 8 pad : 80B row stride, 16B aligned, ldmatrix conflict-free

template<int EPI, bool A_F32, bool B_F32, bool OUT_BF16>
__global__ __launch_bounds__(256, 2)
void gemm_bf16(const void* __restrict__ Ag, int lda, size_t strA,
               const void* __restrict__ Bg, int ldb, size_t strB,
               void* __restrict__ Og, int ldo, size_t strO,
               int K, const float* __restrict__ bias,
               const float* __restrict__ X, size_t strX, float scale) {
    __shared__ __align__(16) __nv_bfloat16 sAm[2][128 * SROW];
    __shared__ __align__(16) __nv_bfloat16 sBm[2][128 * SROW];

    const int tid = threadIdx.x, lane = tid & 31, warp = tid >> 5;
    const int wm = warp >> 2, wn = warp & 3;
    const int g = lane >> 2, tig = lane & 3;
    const int mBase = blockIdx.y * 128, nBase = blockIdx.x * 128;
    const int ldRow = tid >> 2;          // 0..63
    const int ldCol = (tid & 3) * 8;     // 0,8,16,24

    float acc[4][4][4];
    #pragma unroll
    for (int i = 0; i < 4; i++)
        #pragma unroll
        for (int j = 0; j < 4; j++)
            #pragma unroll
            for (int r = 0; r < 4; r++) acc[i][j][r] = 0.f;

    auto loadA = [&](int k0, uint4* r) {
        #pragma unroll
        for (int it = 0; it < 2; it++) {
            if constexpr (A_F32) {
                const float* p = (const float*)Ag + (size_t)blockIdx.z * strA
                               + (size_t)(mBase + ldRow + it * 64) * lda + k0 + ldCol;
                float4 f0 = *(const float4*)p;
                float4 f1 = *(const float4*)(p + 4);
                r[it] = pack8(f0, f1);
            } else {
                const __nv_bfloat16* p = (const __nv_bfloat16*)Ag + (size_t)blockIdx.z * strA
                                       + (size_t)(mBase + ldRow + it * 64) * lda + k0 + ldCol;
                r[it] = *(const uint4*)p;
            }
        }
    };
    auto loadB = [&](int k0, uint4* r) {
        #pragma unroll
        for (int it = 0; it < 2; it++) {
            if constexpr (B_F32) {
                const float* p = (const float*)Bg + (size_t)blockIdx.z * strB
                               + (size_t)(nBase + ldRow + it * 64) * ldb + k0 + ldCol;
                float4 f0 = *(const float4*)p;
                float4 f1 = *(const float4*)(p + 4);
                r[it] = pack8(f0, f1);
            } else {
                const __nv_bfloat16* p = (const __nv_bfloat16*)Bg + (size_t)blockIdx.z * strB
                                       + (size_t)(nBase + ldRow + it * 64) * ldb + k0 + ldCol;
                r[it] = *(const uint4*)p;
            }
        }
    };
    auto sts = [&](int buf, const uint4* ra, const uint4* rb) {
        #pragma unroll
        for (int it = 0; it < 2; it++) {
            *(uint4*)&sAm[buf][(ldRow + it * 64) * SROW + ldCol] = ra[it];
            *(uint4*)&sBm[buf][(ldRow + it * 64) * SROW + ldCol] = rb[it];
        }
    };

    const int nk = K >> 5;
    uint4 ra[2], rb[2];
    loadA(0, ra); loadB(0, rb);
    sts(0, ra, rb);
    __syncthreads();

    for (int kt = 0; kt < nk; kt++) {
        const int cur = kt & 1;
        if (kt + 1 < nk) { loadA((kt + 1) << 5, ra); loadB((kt + 1) << 5, rb); }

        #pragma unroll
        for (int ks = 0; ks < 2; ks++) {
            uint32_t af[4][4], bf[4][2];
            #pragma unroll
            for (int mt = 0; mt < 4; mt++) {
                const __nv_bfloat16* p = &sAm[cur][(wm * 64 + mt * 16 + (lane & 15)) * SROW
                                                   + ks * 16 + ((lane >> 4) << 3)];
                ldsm4(af[mt], p);
            }
            #pragma unroll
            for (int np = 0; np < 2; np++) {
                const __nv_bfloat16* p = &sBm[cur][(wn * 32 + np * 16 + (lane & 7) + ((lane >> 4) << 3)) * SROW
                                                   + ks * 16 + (((lane >> 3) & 1) << 3)];
                uint32_t t[4];
                ldsm4(t, p);
                bf[np * 2][0] = t[0]; bf[np * 2][1] = t[1];
                bf[np * 2 + 1][0] = t[2]; bf[np * 2 + 1][1] = t[3];
            }
            #pragma unroll
            for (int mt = 0; mt < 4; mt++)
                #pragma unroll
                for (int nt = 0; nt < 4; nt++)
                    mma16(acc[mt][nt], af[mt], bf[nt]);
        }

        if (kt + 1 < nk) {
            sts(cur ^ 1, ra, rb);
            __syncthreads();
        }
    }

    // ---- epilogue ----
    float bn0[4], bn1[4];
    if (EPI == 4) {
        #pragma unroll
        for (int nt = 0; nt < 4; nt++) {
            int col = nBase + wn * 32 + nt * 8 + tig * 2;
            bn0[nt] = bias[col]; bn1[nt] = bias[col + 1];
        }
    }
    #pragma unroll
    for (int mt = 0; mt < 4; mt++) {
        #pragma unroll
        for (int half = 0; half < 2; half++) {
            const int row = mBase + wm * 64 + mt * 16 + g + half * 8;
            float bm = (EPI == 1 || EPI == 2) ? bias[row] : 0.f;
            #pragma unroll
            for (int nt = 0; nt < 4; nt++) {
                const int col = nBase + wn * 32 + nt * 8 + tig * 2;
                float v0 = acc[mt][nt][half * 2 + 0];
                float v1 = acc[mt][nt][half * 2 + 1];
                if (EPI == 3) { v0 *= scale; v1 *= scale; }
                if (EPI == 1 || EPI == 2) { v0 += bm; v1 += bm; }
                if (EPI == 4) { v0 += bn0[nt]; v1 += bn1[nt]; }
                if (EPI == 2) {
                    const float* xr = X + (size_t)blockIdx.z * strX + (size_t)row * ldo + col;
                    v0 += xr[0]; v1 += xr[1];
                }
                if constexpr (OUT_BF16) {
                    __nv_bfloat16* Ob = (__nv_bfloat16*)Og + (size_t)blockIdx.z * strO;
                    __nv_bfloat162 st;
                    st.x = __float2bfloat16_rn(v0);
                    st.y = __float2bfloat16_rn(v1);
                    *(__nv_bfloat162*)(Ob + (size_t)row * ldo + col) = st;
                } else {
                    float* Ob = (float*)Og + (size_t)blockIdx.z * strO;
                    float2 st = { v0, v1 };
                    *(float2*)(Ob + (size_t)row * ldo + col) = st;
                }
            }
        }
    }
}

// ---------------------------------------------------------------------------
// Fused softmax: fp32 scores in, bf16 probabilities out.  One pass in regs.
// grid = B*L, 256 threads; row of 2048 = 8 floats/thread.
// ---------------------------------------------------------------------------
__global__ __launch_bounds__(256)
void softmax_bf16(const float* __restrict__ w, __nv_bfloat16* __restrict__ wb) {
    const float4* p = (const float4*)(w + (size_t)blockIdx.x * LL);
    const int tid = threadIdx.x;
    float4 v0 = p[tid], v1 = p[tid + 256];

    __shared__ float red[8];
    const int lane = tid & 31, wid = tid >> 5;

    float m = fmaxf(fmaxf(fmaxf(v0.x, v0.y), fmaxf(v0.z, v0.w)),
                    fmaxf(fmaxf(v1.x, v1.y), fmaxf(v1.z, v1.w)));
    m = warp_max(m);
    if (lane == 0) red[wid] = m;
    __syncthreads();
    if (wid == 0) {
        m = (lane < 8) ? red[lane] : -1e30f;
        m = warp_max(m);
        if (lane == 0) red[0] = m;
    }
    __syncthreads();
    m = red[0];
    __syncthreads();

    v0.x = __expf(v0.x - m); v0.y = __expf(v0.y - m);
    v0.z = __expf(v0.z - m); v0.w = __expf(v0.w - m);
    v1.x = __expf(v1.x - m); v1.y = __expf(v1.y - m);
    v1.z = __expf(v1.z - m); v1.w = __expf(v1.w - m);
    float s = (v0.x + v0.y) + (v0.z + v0.w) + (v1.x + v1.y) + (v1.z + v1.w);
    s = warp_sum(s);
    if (lane == 0) red[wid] = s;
    __syncthreads();
    if (wid == 0) {
        s = (lane < 8) ? red[lane] : 0.f;
        s = warp_sum(s);
        if (lane == 0) red[0] = s;
    }
    __syncthreads();
    const float inv = 1.0f / red[0];

    uint2* ob = (uint2*)(wb + (size_t)blockIdx.x * LL);
    uint2 o0, o1;
    o0.x = packbf2(v0.x * inv, v0.y * inv);
    o0.y = packbf2(v0.z * inv, v0.w * inv);
    o1.x = packbf2(v1.x * inv, v1.y * inv);
    o1.y = packbf2(v1.z * inv, v1.w * inv);
    ob[tid] = o0;
    ob[tid + 256] = o1;
}

// ---------------------------------------------------------------------------
// Launch
// ---------------------------------------------------------------------------
extern "C" void kernel_launch(void* const* d_in, const int* in_sizes, int n_in,
                              void* d_out, int out_size) {
    const float* x        = (const float*)d_in[0];
    const float* gn_gamma = (const float*)d_in[1];
    const float* gn_beta  = (const float*)d_in[2];
    const float* Wq = (const float*)d_in[3];
    const float* bq = (const float*)d_in[4];
    const float* Wk = (const float*)d_in[5];
    const float* bk = (const float*)d_in[6];
    const float* Wv = (const float*)d_in[7];
    const float* bv = (const float*)d_in[8];
    const float* Wo = (const float*)d_in[9];
    const float* bo = (const float*)d_in[10];
    float* out = (float*)d_out;

    __nv_bfloat16 *hT, *qT, *kT, *v, *aT, *wb;
    float* w; float2* stats;
    cudaGetSymbolAddress((void**)&hT, g_hT);
    cudaGetSymbolAddress((void**)&qT, g_qT);
    cudaGetSymbolAddress((void**)&kT, g_kT);
    cudaGetSymbolAddress((void**)&v,  g_v);
    cudaGetSymbolAddress((void**)&aT, g_aT);
    cudaGetSymbolAddress((void**)&w,  g_w);
    cudaGetSymbolAddress((void**)&wb, g_wb);
    cudaGetSymbolAddress((void**)&stats, g_stats);

    const size_t CL  = (size_t)CC * LL;
    const size_t LLs = (size_t)LL * LL;
    const float scale = 0.044194173824159216f;   // 1/sqrt(512)

    // 1. GroupNorm (stats + normalize/transpose to bf16 hT[l][c])
    gn_stats<<<BATCH * NGROUPS, 512>>>(x, stats);
    gn_norm_t<<<dim3(LL / 32, CC / 64, BATCH), 256>>>(x, stats, gn_gamma, gn_beta, hT);

    // 2. qT[l][o] = hT @ Wq^T + bq   (M=L, N=C, K=C)  -> bf16
    dim3 gT(CC / 128, LL / 128, BATCH);
    gemm_bf16<4, false, true, true><<<gT, 256>>>(hT, CC, CL, Wq, CC, 0, qT, CC, CL,
                                                 CC, bq, nullptr, 0, 0.f);
    gemm_bf16<4, false, true, true><<<gT, 256>>>(hT, CC, CL, Wk, CC, 0, kT, CC, CL,
                                                 CC, bk, nullptr, 0, 0.f);
    //    v[c][l] = Wv @ h + bv       (M=C, N=L, K=C)  -> bf16
    dim3 gV(LL / 128, CC / 128, BATCH);
    gemm_bf16<1, true, false, true><<<gV, 256>>>(Wv, CC, 0, hT, CC, CL, v, LL, CL,
                                                 CC, bv, nullptr, 0, 0.f);

    // 3. scores w[i][j] = scale * qT @ kT^T   (M=N=L, K=C) -> fp32
    dim3 gS(LL / 128, LL / 128, BATCH);
    gemm_bf16<3, false, false, false><<<gS, 256>>>(qT, CC, CL, kT, CC, CL, w, LL, LLs,
                                                   CC, nullptr, nullptr, 0, scale);

    // 4. softmax rows -> bf16
    softmax_bf16<<<BATCH * LL, 256>>>(w, wb);

    // 5. aT[i][c] = wb @ v^T          (M=L, N=C, K=L) -> bf16
    gemm_bf16<0, false, false, true><<<gT, 256>>>(wb, LL, LLs, v, LL, CL, aT, CC, CL,
                                                  LL, nullptr, nullptr, 0, 0.f);

    // 6. out[o][l] = x + Wo @ aT^T + bo   (M=C, N=L, K=C) -> fp32
    gemm_bf16<2, true, false, false><<<gV, 256>>>(Wo, CC, 0, aT, CC, CL, out, LL, CL,
                                                  CC, bo, x, CL, 0.f);
}

// round 7
// speedup vs baseline: 1.9313x; 1.0694x over previous
#include <cuda_runtime.h>
#include <cuda_bf16.h>
#include <cstdint>
#include <cstddef>

#define BATCH 8
#define CC    512
#define LL    2048
#define NGROUPS 32
#define CPG   (CC / NGROUPS)
#define GROUP_ELEMS (CPG * LL)
#define EPS   1e-5f

// ---------------------------------------------------------------------------
// Device scratch (all GEMM operands k-contiguous)
// ---------------------------------------------------------------------------
__device__ __nv_bfloat16 g_hT[(size_t)BATCH * LL * CC];   // [b][l][c]
__device__ __nv_bfloat16 g_qT[(size_t)BATCH * LL * CC];   // [b][l][c]
__device__ __nv_bfloat16 g_kT[(size_t)BATCH * LL * CC];   // [b][l][c]
__device__ __nv_bfloat16 g_v [(size_t)BATCH * CC * LL];   // [b][c][l]
__device__ __nv_bfloat16 g_aT[(size_t)BATCH * LL * CC];   // [b][l][c]
__device__ __nv_bfloat16 g_e [(size_t)BATCH * LL * LL];   // exp(scores) bf16
__device__ float         g_part[(size_t)BATCH * LL * 64]; // rowsum partials
__device__ float         g_invrs[(size_t)BATCH * LL];     // 1/rowsum
__device__ float2        g_stats[BATCH * NGROUPS];

// ---------------------------------------------------------------------------
// Helpers
// ---------------------------------------------------------------------------
__device__ __forceinline__ float warp_sum(float v) {
    #pragma unroll
    for (int o = 16; o > 0; o >>= 1) v += __shfl_xor_sync(0xffffffffu, v, o);
    return v;
}
__device__ __forceinline__ void ldsm4(uint32_t* r, const void* p) {
    uint32_t a = (uint32_t)__cvta_generic_to_shared(p);
    asm volatile("ldmatrix.sync.aligned.m8n8.x4.shared.b16 {%0,%1,%2,%3}, [%4];"
                 : "=r"(r[0]), "=r"(r[1]), "=r"(r[2]), "=r"(r[3]) : "r"(a));
}
__device__ __forceinline__ void mma16(float* d, const uint32_t* a, const uint32_t* b) {
    asm volatile(
        "mma.sync.aligned.m16n8k16.row.col.f32.bf16.bf16.f32 "
        "{%0,%1,%2,%3}, {%4,%5,%6,%7}, {%8,%9}, {%0,%1,%2,%3};\n"
        : "+f"(d[0]), "+f"(d[1]), "+f"(d[2]), "+f"(d[3])
        : "r"(a[0]), "r"(a[1]), "r"(a[2]), "r"(a[3]), "r"(b[0]), "r"(b[1]));
}
__device__ __forceinline__ uint32_t packbf2(float x, float y) {
    __nv_bfloat162 t = __floats2bfloat162_rn(x, y);
    return *(uint32_t*)&t;
}
__device__ __forceinline__ uint4 pack8(float4 a, float4 b) {
    uint4 r;
    r.x = packbf2(a.x, a.y); r.y = packbf2(a.z, a.w);
    r.z = packbf2(b.x, b.y); r.w = packbf2(b.z, b.w);
    return r;
}
__device__ __forceinline__ void cp16(void* smem_dst, const void* gmem_src) {
    uint32_t d = (uint32_t)__cvta_generic_to_shared(smem_dst);
    asm volatile("cp.async.cg.shared.global [%0], [%1], 16;" :: "r"(d), "l"(gmem_src));
}
__device__ __forceinline__ void cp_commit() {
    asm volatile("cp.async.commit_group;" ::: "memory");
}
__device__ __forceinline__ void cp_wait1() {
    asm volatile("cp.async.wait_group 1;" ::: "memory");
}

// ---------------------------------------------------------------------------
// GroupNorm pass 1 (stats)
// ---------------------------------------------------------------------------
__global__ void gn_stats(const float* __restrict__ x, float2* __restrict__ stats) {
    const int bg = blockIdx.x;
    const int b  = bg / NGROUPS;
    const int g  = bg % NGROUPS;
    const size_t base = ((size_t)b * CC + (size_t)g * CPG) * LL;
    const float* xp = x + base;

    float s = 0.f, s2 = 0.f;
    for (int i = threadIdx.x; i < GROUP_ELEMS; i += blockDim.x) {
        float v = xp[i];
        s += v; s2 += v * v;
    }
    __shared__ float red1[16], red2[16];
    s = warp_sum(s); s2 = warp_sum(s2);
    const int lane = threadIdx.x & 31, wid = threadIdx.x >> 5;
    if (lane == 0) { red1[wid] = s; red2[wid] = s2; }
    __syncthreads();
    if (threadIdx.x == 0) {
        float t = 0.f, t2 = 0.f;
        #pragma unroll
        for (int i = 0; i < 16; i++) { t += red1[i]; t2 += red2[i]; }
        float mean = t * (1.0f / GROUP_ELEMS);
        float var  = t2 * (1.0f / GROUP_ELEMS) - mean * mean;
        stats[bg] = make_float2(mean, rsqrtf(var + EPS));
    }
}

// ---------------------------------------------------------------------------
// GroupNorm pass 2: normalize + transpose + bf16 -> hT[b][l][c]
// ---------------------------------------------------------------------------
__global__ void gn_norm_t(const float* __restrict__ x,
                          const float2* __restrict__ stats,
                          const float* __restrict__ gamma,
                          const float* __restrict__ beta,
                          __nv_bfloat16* __restrict__ hT) {
    const int b = blockIdx.z;
    const int l0 = blockIdx.x * 32;
    const int c0 = blockIdx.y * 64;
    const int tx = threadIdx.x & 31, ty = threadIdx.x >> 5;
    __shared__ float tile[64][33];

    const float* xb = x + (size_t)b * CC * LL;
    #pragma unroll
    for (int i = 0; i < 8; i++) {
        int c = c0 + i * 8 + ty;
        float2 st = stats[b * NGROUPS + (c >> 4)];
        float gm = gamma[c], bt = beta[c];
        float xv = xb[(size_t)c * LL + l0 + tx];
        tile[c - c0][tx] = (xv - st.x) * st.y * gm + bt;
    }
    __syncthreads();
    __nv_bfloat16* ht = hT + (size_t)b * LL * CC;
    #pragma unroll
    for (int i = 0; i < 4; i++) {
        int l = i * 8 + ty;
        __nv_bfloat162 o;
        o.x = __float2bfloat16_rn(tile[tx * 2][l]);
        o.y = __float2bfloat16_rn(tile[tx * 2 + 1][l]);
        *(__nv_bfloat162*)(ht + (size_t)(l0 + l) * CC + c0 + tx * 2) = o;
    }
}

// ---------------------------------------------------------------------------
// bf16 mma.sync GEMM, 3-stage cp.async pipeline.
//   out[b,m,n] = sum_k A[m,k] * B[n,k]  (+ epilogue)
// EPI: 1 +bias[m] ; 2 +bias[m]+X, fp32 out ; 3 exp(v*scale) + rowsum partials
//      4 +bias[n] ; 5 *aux[m] (inv rowsum)
// Tile 128x128xBK32, 8 warps (2x4), warp 64x32, m16n8k16.
// ---------------------------------------------------------------------------
#define SROW 40        // 32 + 8 pad (80B rows: 16B aligned, ldmatrix conflict-free)
#define STG_ELEM (128 * SROW)
#define SM_TOTAL (6 * STG_ELEM * 2)   // 3 stages x (A+B), bf16 = 61440 B

template<int EPI, bool A_F32, bool B_F32, bool OUT_BF16>
__global__ __launch_bounds__(256, 2)
void gemm_cp(const void* __restrict__ Ag, int lda, size_t strA,
             const void* __restrict__ Bg, int ldb, size_t strB,
             void* __restrict__ Og, int ldo, size_t strO,
             int K, const float* __restrict__ bias,
             const float* __restrict__ X, size_t strX,
             float scale, float* __restrict__ aux) {
    extern __shared__ __align__(16) __nv_bfloat16 smem[];
    __nv_bfloat16* smA = smem;                 // 3 stages
    __nv_bfloat16* smB = smem + 3 * STG_ELEM;  // 3 stages

    const int tid = threadIdx.x, lane = tid & 31, warp = tid >> 5;
    const int wm = warp >> 2, wn = warp & 3;
    const int g = lane >> 2, tig = lane & 3;
    const int mBase = blockIdx.y * 128, nBase = blockIdx.x * 128;
    const int z = blockIdx.z;
    const int ldRow = tid >> 2;           // 0..63
    const int ldCol8 = (tid & 3) * 8;     // bf16 elems: 0,8,16,24

    const int nk = K >> 5;

    auto issue_stage = [&](int kt) {
        if (kt < nk) {
            const int buf = kt % 3;
            const int k0 = kt << 5;
            __nv_bfloat16* sA = smA + buf * STG_ELEM;
            __nv_bfloat16* sB = smB + buf * STG_ELEM;
            #pragma unroll
            for (int it = 0; it < 2; it++) {
                const int row = ldRow + it * 64;
                if constexpr (A_F32) {
                    const float* p = (const float*)Ag + strA * z
                                   + (size_t)(mBase + row) * lda + k0 + ldCol8;
                    *(uint4*)(sA + row * SROW + ldCol8) =
                        pack8(*(const float4*)p, *(const float4*)(p + 4));
                } else {
                    const __nv_bfloat16* p = (const __nv_bfloat16*)Ag + strA * z
                                           + (size_t)(mBase + row) * lda + k0 + ldCol8;
                    cp16(sA + row * SROW + ldCol8, p);
                }
                if constexpr (B_F32) {
                    const float* p = (const float*)Bg + strB * z
                                   + (size_t)(nBase + row) * ldb + k0 + ldCol8;
                    *(uint4*)(sB + row * SROW + ldCol8) =
                        pack8(*(const float4*)p, *(const float4*)(p + 4));
                } else {
                    const __nv_bfloat16* p = (const __nv_bfloat16*)Bg + strB * z
                                           + (size_t)(nBase + row) * ldb + k0 + ldCol8;
                    cp16(sB + row * SROW + ldCol8, p);
                }
            }
        }
        cp_commit();
    };

    float acc[4][4][4];
    #pragma unroll
    for (int i = 0; i < 4; i++)
        #pragma unroll
        for (int j = 0; j < 4; j++)
            #pragma unroll
            for (int r = 0; r < 4; r++) acc[i][j][r] = 0.f;

    issue_stage(0);
    issue_stage(1);

    for (int kt = 0; kt < nk; kt++) {
        cp_wait1();
        __syncthreads();
        issue_stage(kt + 2);

        const int buf = kt % 3;
        const __nv_bfloat16* sA = smA + buf * STG_ELEM;
        const __nv_bfloat16* sB = smB + buf * STG_ELEM;

        #pragma unroll
        for (int ks = 0; ks < 2; ks++) {
            uint32_t af[4][4], bf[4][2];
            #pragma unroll
            for (int mt = 0; mt < 4; mt++) {
                const __nv_bfloat16* p = &sA[(wm * 64 + mt * 16 + (lane & 15)) * SROW
                                             + ks * 16 + ((lane >> 4) << 3)];
                ldsm4(af[mt], p);
            }
            #pragma unroll
            for (int np = 0; np < 2; np++) {
                const __nv_bfloat16* p = &sB[(wn * 32 + np * 16 + (lane & 7) + ((lane >> 4) << 3)) * SROW
                                             + ks * 16 + (((lane >> 3) & 1) << 3)];
                uint32_t t[4];
                ldsm4(t, p);
                bf[np * 2][0] = t[0]; bf[np * 2][1] = t[1];
                bf[np * 2 + 1][0] = t[2]; bf[np * 2 + 1][1] = t[3];
            }
            #pragma unroll
            for (int mt = 0; mt < 4; mt++)
                #pragma unroll
                for (int nt = 0; nt < 4; nt++)
                    mma16(acc[mt][nt], af[mt], bf[nt]);
        }
        __syncthreads();
    }

    // ---- epilogue ----
    float bn0[4], bn1[4];
    if (EPI == 4) {
        #pragma unroll
        for (int nt = 0; nt < 4; nt++) {
            int col = nBase + wn * 32 + nt * 8 + tig * 2;
            bn0[nt] = bias[col]; bn1[nt] = bias[col + 1];
        }
    }
    #pragma unroll
    for (int mt = 0; mt < 4; mt++) {
        #pragma unroll
        for (int half = 0; half < 2; half++) {
            const int row = mBase + wm * 64 + mt * 16 + g + half * 8;
            float bm = (EPI == 1 || EPI == 2) ? bias[row] : 0.f;
            float rsmul = (EPI == 5) ? aux[(size_t)z * LL + row] : 0.f;
            float rsum = 0.f;
            #pragma unroll
            for (int nt = 0; nt < 4; nt++) {
                const int col = nBase + wn * 32 + nt * 8 + tig * 2;
                float v0 = acc[mt][nt][half * 2 + 0];
                float v1 = acc[mt][nt][half * 2 + 1];
                if (EPI == 1 || EPI == 2) { v0 += bm; v1 += bm; }
                if (EPI == 4) { v0 += bn0[nt]; v1 += bn1[nt]; }
                if (EPI == 5) { v0 *= rsmul; v1 *= rsmul; }
                if (EPI == 2) {
                    const float* xr = X + strX * z + (size_t)row * ldo + col;
                    v0 += xr[0]; v1 += xr[1];
                }
                if (EPI == 3) {
                    v0 = __expf(v0 * scale);
                    v1 = __expf(v1 * scale);
                    __nv_bfloat162 st = __floats2bfloat162_rn(v0, v1);
                    *(__nv_bfloat162*)((__nv_bfloat16*)Og + strO * z
                                       + (size_t)row * ldo + col) = st;
                    rsum += __bfloat162float(st.x) + __bfloat162float(st.y);
                } else if constexpr (OUT_BF16) {
                    __nv_bfloat162 st = __floats2bfloat162_rn(v0, v1);
                    *(__nv_bfloat162*)((__nv_bfloat16*)Og + strO * z
                                       + (size_t)row * ldo + col) = st;
                } else {
                    float2 st = { v0, v1 };
                    *(float2*)((float*)Og + strO * z + (size_t)row * ldo + col) = st;
                }
            }
            if (EPI == 3) {
                rsum += __shfl_xor_sync(0xffffffffu, rsum, 1);
                rsum += __shfl_xor_sync(0xffffffffu, rsum, 2);
                if (tig == 0)
                    aux[((size_t)z * LL + row) * 64 + blockIdx.x * 4 + wn] = rsum;
            }
        }
    }
}

// ---------------------------------------------------------------------------
// Rowsum reduce: 64 partials per row -> 1/rowsum
// ---------------------------------------------------------------------------
__global__ __launch_bounds__(256)
void rs_reduce(const float* __restrict__ part, float* __restrict__ invrs) {
    const int row = blockIdx.x * 8 + (threadIdx.x >> 5);
    const int lane = threadIdx.x & 31;
    const float* p = part + (size_t)row * 64;
    float s = p[lane] + p[lane + 32];
    s = warp_sum(s);
    if (lane == 0) invrs[row] = 1.0f / s;
}

// ---------------------------------------------------------------------------
// Launch
// ---------------------------------------------------------------------------
extern "C" void kernel_launch(void* const* d_in, const int* in_sizes, int n_in,
                              void* d_out, int out_size) {
    const float* x        = (const float*)d_in[0];
    const float* gn_gamma = (const float*)d_in[1];
    const float* gn_beta  = (const float*)d_in[2];
    const float* Wq = (const float*)d_in[3];
    const float* bq = (const float*)d_in[4];
    const float* Wk = (const float*)d_in[5];
    const float* bk = (const float*)d_in[6];
    const float* Wv = (const float*)d_in[7];
    const float* bv = (const float*)d_in[8];
    const float* Wo = (const float*)d_in[9];
    const float* bo = (const float*)d_in[10];
    float* out = (float*)d_out;

    __nv_bfloat16 *hT, *qT, *kT, *v, *aT, *e;
    float *part, *invrs; float2* stats;
    cudaGetSymbolAddress((void**)&hT, g_hT);
    cudaGetSymbolAddress((void**)&qT, g_qT);
    cudaGetSymbolAddress((void**)&kT, g_kT);
    cudaGetSymbolAddress((void**)&v,  g_v);
    cudaGetSymbolAddress((void**)&aT, g_aT);
    cudaGetSymbolAddress((void**)&e,  g_e);
    cudaGetSymbolAddress((void**)&part, g_part);
    cudaGetSymbolAddress((void**)&invrs, g_invrs);
    cudaGetSymbolAddress((void**)&stats, g_stats);

    const size_t CL  = (size_t)CC * LL;
    const size_t LLs = (size_t)LL * LL;
    const float scale = 0.044194173824159216f;   // 1/sqrt(512)

    cudaFuncSetAttribute(gemm_cp<4, false, true,  true>,
                         cudaFuncAttributeMaxDynamicSharedMemorySize, SM_TOTAL);
    cudaFuncSetAttribute(gemm_cp<1, true,  false, true>,
                         cudaFuncAttributeMaxDynamicSharedMemorySize, SM_TOTAL);
    cudaFuncSetAttribute(gemm_cp<3, false, false, true>,
                         cudaFuncAttributeMaxDynamicSharedMemorySize, SM_TOTAL);
    cudaFuncSetAttribute(gemm_cp<5, false, false, true>,
                         cudaFuncAttributeMaxDynamicSharedMemorySize, SM_TOTAL);
    cudaFuncSetAttribute(gemm_cp<2, true,  false, false>,
                         cudaFuncAttributeMaxDynamicSharedMemorySize, SM_TOTAL);

    // 1. GroupNorm
    gn_stats<<<BATCH * NGROUPS, 512>>>(x, stats);
    gn_norm_t<<<dim3(LL / 32, CC / 64, BATCH), 256>>>(x, stats, gn_gamma, gn_beta, hT);

    // 2. qT[l][o] = hT @ Wq^T + bq   (M=L, N=C, K=C)
    dim3 gT(CC / 128, LL / 128, BATCH);
    gemm_cp<4, false, true, true><<<gT, 256, SM_TOTAL>>>(
        hT, CC, CL, Wq, CC, 0, qT, CC, CL, CC, bq, nullptr, 0, 0.f, nullptr);
    gemm_cp<4, false, true, true><<<gT, 256, SM_TOTAL>>>(
        hT, CC, CL, Wk, CC, 0, kT, CC, CL, CC, bk, nullptr, 0, 0.f, nullptr);
    //    v[c][l] = Wv @ h + bv   (M=C, N=L, K=C)
    dim3 gV(LL / 128, CC / 128, BATCH);
    gemm_cp<1, true, false, true><<<gV, 256, SM_TOTAL>>>(
        Wv, CC, 0, hT, CC, CL, v, LL, CL, CC, bv, nullptr, 0, 0.f, nullptr);

    // 3. e[i][j] = exp(scale * qT@kT^T), + rowsum partials  (M=N=L, K=C)
    dim3 gS(LL / 128, LL / 128, BATCH);
    gemm_cp<3, false, false, true><<<gS, 256, SM_TOTAL>>>(
        qT, CC, CL, kT, CC, CL, e, LL, LLs, CC, nullptr, nullptr, 0, scale, part);

    // 4. 1/rowsum
    rs_reduce<<<BATCH * LL / 8, 256>>>(part, invrs);

    // 5. aT[i][c] = (e @ v^T) * invrs[i]   (M=L, N=C, K=L)
    gemm_cp<5, false, false, true><<<gT, 256, SM_TOTAL>>>(
        e, LL, LLs, v, LL, CL, aT, CC, CL, LL, nullptr, nullptr, 0, 0.f, invrs);

    // 6. out[o][l] = x + Wo @ aT^T + bo   (M=C, N=L, K=C)
    gemm_cp<2, true, false, false><<<gV, 256, SM_TOTAL>>>(
        Wo, CC, 0, aT, CC, CL, out, LL, CL, CC, bo, x, CL, 0.f, nullptr);
}

// round 8
// speedup vs baseline: 2.0273x; 1.0497x over previous
#include <cuda_runtime.h>
#include <cuda_bf16.h>
#include <cstdint>
#include <cstddef>

#define BATCH 8
#define CC    512
#define LL    2048
#define NGROUPS 32
#define CPG   (CC / NGROUPS)
#define GROUP_ELEMS (CPG * LL)
#define EPS   1e-5f

// ---------------------------------------------------------------------------
// Device scratch (all GEMM operands k-contiguous)
// ---------------------------------------------------------------------------
__device__ __nv_bfloat16 g_hT[(size_t)BATCH * LL * CC];   // [b][l][c]
__device__ __nv_bfloat16 g_qT[(size_t)BATCH * LL * CC];   // [b][l][c]
__device__ __nv_bfloat16 g_kT[(size_t)BATCH * LL * CC];   // [b][l][c]
__device__ __nv_bfloat16 g_v [(size_t)BATCH * CC * LL];   // [b][c][l]
__device__ __nv_bfloat16 g_aT[(size_t)BATCH * LL * CC];   // [b][l][c]
__device__ __nv_bfloat16 g_e [(size_t)BATCH * LL * LL];   // exp(scores) bf16
__device__ float         g_part[(size_t)BATCH * LL * 64]; // rowsum partials
__device__ float         g_invrs[(size_t)BATCH * LL];     // 1/rowsum
__device__ float2        g_stats[BATCH * NGROUPS];

// ---------------------------------------------------------------------------
// Helpers
// ---------------------------------------------------------------------------
__device__ __forceinline__ float warp_sum(float v) {
    #pragma unroll
    for (int o = 16; o > 0; o >>= 1) v += __shfl_xor_sync(0xffffffffu, v, o);
    return v;
}
__device__ __forceinline__ void ldsm4(uint32_t* r, const void* p) {
    uint32_t a = (uint32_t)__cvta_generic_to_shared(p);
    asm volatile("ldmatrix.sync.aligned.m8n8.x4.shared.b16 {%0,%1,%2,%3}, [%4];"
                 : "=r"(r[0]), "=r"(r[1]), "=r"(r[2]), "=r"(r[3]) : "r"(a));
}
__device__ __forceinline__ void mma16(float* d, const uint32_t* a, const uint32_t* b) {
    asm volatile(
        "mma.sync.aligned.m16n8k16.row.col.f32.bf16.bf16.f32 "
        "{%0,%1,%2,%3}, {%4,%5,%6,%7}, {%8,%9}, {%0,%1,%2,%3};\n"
        : "+f"(d[0]), "+f"(d[1]), "+f"(d[2]), "+f"(d[3])
        : "r"(a[0]), "r"(a[1]), "r"(a[2]), "r"(a[3]), "r"(b[0]), "r"(b[1]));
}
__device__ __forceinline__ uint32_t packbf2(float x, float y) {
    __nv_bfloat162 t = __floats2bfloat162_rn(x, y);
    return *(uint32_t*)&t;
}
__device__ __forceinline__ uint4 pack8(float4 a, float4 b) {
    uint4 r;
    r.x = packbf2(a.x, a.y); r.y = packbf2(a.z, a.w);
    r.z = packbf2(b.x, b.y); r.w = packbf2(b.z, b.w);
    return r;
}
__device__ __forceinline__ void cp16(void* smem_dst, const void* gmem_src) {
    uint32_t d = (uint32_t)__cvta_generic_to_shared(smem_dst);
    asm volatile("cp.async.cg.shared.global [%0], [%1], 16;" :: "r"(d), "l"(gmem_src));
}
__device__ __forceinline__ void cp_commit() {
    asm volatile("cp.async.commit_group;" ::: "memory");
}
__device__ __forceinline__ void cp_wait1() {
    asm volatile("cp.async.wait_group 1;" ::: "memory");
}

// ---------------------------------------------------------------------------
// GroupNorm pass 1 (stats)
// ---------------------------------------------------------------------------
__global__ void gn_stats(const float* __restrict__ x, float2* __restrict__ stats) {
    const int bg = blockIdx.x;
    const int b  = bg / NGROUPS;
    const int g  = bg % NGROUPS;
    const size_t base = ((size_t)b * CC + (size_t)g * CPG) * LL;
    const float* xp = x + base;

    float s = 0.f, s2 = 0.f;
    for (int i = threadIdx.x; i < GROUP_ELEMS; i += blockDim.x) {
        float v = xp[i];
        s += v; s2 += v * v;
    }
    __shared__ float red1[16], red2[16];
    s = warp_sum(s); s2 = warp_sum(s2);
    const int lane = threadIdx.x & 31, wid = threadIdx.x >> 5;
    if (lane == 0) { red1[wid] = s; red2[wid] = s2; }
    __syncthreads();
    if (threadIdx.x == 0) {
        float t = 0.f, t2 = 0.f;
        #pragma unroll
        for (int i = 0; i < 16; i++) { t += red1[i]; t2 += red2[i]; }
        float mean = t * (1.0f / GROUP_ELEMS);
        float var  = t2 * (1.0f / GROUP_ELEMS) - mean * mean;
        stats[bg] = make_float2(mean, rsqrtf(var + EPS));
    }
}

// ---------------------------------------------------------------------------
// GroupNorm pass 2: normalize + transpose + bf16 -> hT[b][l][c]
// ---------------------------------------------------------------------------
__global__ void gn_norm_t(const float* __restrict__ x,
                          const float2* __restrict__ stats,
                          const float* __restrict__ gamma,
                          const float* __restrict__ beta,
                          __nv_bfloat16* __restrict__ hT) {
    const int b = blockIdx.z;
    const int l0 = blockIdx.x * 32;
    const int c0 = blockIdx.y * 64;
    const int tx = threadIdx.x & 31, ty = threadIdx.x >> 5;
    __shared__ float tile[64][33];

    const float* xb = x + (size_t)b * CC * LL;
    #pragma unroll
    for (int i = 0; i < 8; i++) {
        int c = c0 + i * 8 + ty;
        float2 st = stats[b * NGROUPS + (c >> 4)];
        float gm = gamma[c], bt = beta[c];
        float xv = xb[(size_t)c * LL + l0 + tx];
        tile[c - c0][tx] = (xv - st.x) * st.y * gm + bt;
    }
    __syncthreads();
    __nv_bfloat16* ht = hT + (size_t)b * LL * CC;
    #pragma unroll
    for (int i = 0; i < 4; i++) {
        int l = i * 8 + ty;
        __nv_bfloat162 o;
        o.x = __float2bfloat16_rn(tile[tx * 2][l]);
        o.y = __float2bfloat16_rn(tile[tx * 2 + 1][l]);
        *(__nv_bfloat162*)(ht + (size_t)(l0 + l) * CC + c0 + tx * 2) = o;
    }
}

// ---------------------------------------------------------------------------
// bf16 mma.sync GEMM, 3-stage cp.async + double-buffered register fragments.
//   out[b,m,n] = sum_k A[m,k] * B[n,k]  (+ epilogue)
// EPI: 1 +bias[m] ; 2 +bias[m]+X, fp32 out ; 3 exp(v*scale) + rowsum partials
//      4 +bias[n] ; 5 *aux[m] (inv rowsum)
// Tile 128x128xBK32, 8 warps (2x4), warp 64x32, m16n8k16.
// ---------------------------------------------------------------------------
#define SROW 40        // 32 + 8 pad (80B rows: 16B aligned, ldmatrix conflict-free)
#define STG_ELEM (128 * SROW)
#define SM_TOTAL (6 * STG_ELEM * 2)   // 3 stages x (A+B), bf16 = 61440 B

struct Frags {
    uint32_t a[4][4];
    uint32_t b[4][2];
};

template<int EPI, bool A_F32, bool B_F32, bool OUT_BF16>
__global__ __launch_bounds__(256, 2)
void gemm_cp(const void* __restrict__ Ag, int lda, size_t strA,
             const void* __restrict__ Bg, int ldb, size_t strB,
             void* __restrict__ Og, int ldo, size_t strO,
             int K, const float* __restrict__ bias,
             const float* __restrict__ X, size_t strX,
             float scale, float* __restrict__ aux) {
    extern __shared__ __align__(16) __nv_bfloat16 smem[];
    __nv_bfloat16* smA = smem;                 // 3 stages
    __nv_bfloat16* smB = smem + 3 * STG_ELEM;  // 3 stages

    const int tid = threadIdx.x, lane = tid & 31, warp = tid >> 5;
    const int wm = warp >> 2, wn = warp & 3;
    const int g = lane >> 2, tig = lane & 3;
    const int mBase = blockIdx.y * 128, nBase = blockIdx.x * 128;
    const int z = blockIdx.z;
    const int ldRow = tid >> 2;           // 0..63
    const int ldCol8 = (tid & 3) * 8;     // bf16 elems: 0,8,16,24

    const int nk = K >> 5;

    auto issue_stage = [&](int kt) {
        if (kt < nk) {
            const int buf = kt % 3;
            const int k0 = kt << 5;
            __nv_bfloat16* sA = smA + buf * STG_ELEM;
            __nv_bfloat16* sB = smB + buf * STG_ELEM;
            #pragma unroll
            for (int it = 0; it < 2; it++) {
                const int row = ldRow + it * 64;
                if constexpr (A_F32) {
                    const float* p = (const float*)Ag + strA * z
                                   + (size_t)(mBase + row) * lda + k0 + ldCol8;
                    *(uint4*)(sA + row * SROW + ldCol8) =
                        pack8(*(const float4*)p, *(const float4*)(p + 4));
                } else {
                    const __nv_bfloat16* p = (const __nv_bfloat16*)Ag + strA * z
                                           + (size_t)(mBase + row) * lda + k0 + ldCol8;
                    cp16(sA + row * SROW + ldCol8, p);
                }
                if constexpr (B_F32) {
                    const float* p = (const float*)Bg + strB * z
                                   + (size_t)(nBase + row) * ldb + k0 + ldCol8;
                    *(uint4*)(sB + row * SROW + ldCol8) =
                        pack8(*(const float4*)p, *(const float4*)(p + 4));
                } else {
                    const __nv_bfloat16* p = (const __nv_bfloat16*)Bg + strB * z
                                           + (size_t)(nBase + row) * ldb + k0 + ldCol8;
                    cp16(sB + row * SROW + ldCol8, p);
                }
            }
        }
        cp_commit();
    };

    // batched fragment load for one ks half (all 6 LDSM issued back-to-back)
    auto load_frags = [&](const __nv_bfloat16* sA, const __nv_bfloat16* sB,
                          int ks, Frags& f) {
        #pragma unroll
        for (int mt = 0; mt < 4; mt++) {
            const __nv_bfloat16* p = &sA[(wm * 64 + mt * 16 + (lane & 15)) * SROW
                                         + ks * 16 + ((lane >> 4) << 3)];
            ldsm4(f.a[mt], p);
        }
        #pragma unroll
        for (int np = 0; np < 2; np++) {
            const __nv_bfloat16* p = &sB[(wn * 32 + np * 16 + (lane & 7) + ((lane >> 4) << 3)) * SROW
                                         + ks * 16 + (((lane >> 3) & 1) << 3)];
            uint32_t t[4];
            ldsm4(t, p);
            f.b[np * 2][0] = t[0]; f.b[np * 2][1] = t[1];
            f.b[np * 2 + 1][0] = t[2]; f.b[np * 2 + 1][1] = t[3];
        }
    };

    float acc[4][4][4];
    #pragma unroll
    for (int i = 0; i < 4; i++)
        #pragma unroll
        for (int j = 0; j < 4; j++)
            #pragma unroll
            for (int r = 0; r < 4; r++) acc[i][j][r] = 0.f;

    issue_stage(0);
    issue_stage(1);
    cp_wait1();            // stage 0 resident
    __syncthreads();

    Frags fr[2];
    for (int kt = 0; kt < nk; kt++) {
        const int buf = kt % 3;
        const __nv_bfloat16* sA = smA + buf * STG_ELEM;
        const __nv_bfloat16* sB = smB + buf * STG_ELEM;

        load_frags(sA, sB, 0, fr[0]);      // 6 LDSM, overlapped
        issue_stage(kt + 2);               // fill (kt-1)%3 — readers passed barrier
        load_frags(sA, sB, 1, fr[1]);      // prefetch ks=1 before ks=0 MMAs

        #pragma unroll
        for (int mt = 0; mt < 4; mt++)
            #pragma unroll
            for (int nt = 0; nt < 4; nt++)
                mma16(acc[mt][nt], fr[0].a[mt], fr[0].b[nt]);
        #pragma unroll
        for (int mt = 0; mt < 4; mt++)
            #pragma unroll
            for (int nt = 0; nt < 4; nt++)
                mma16(acc[mt][nt], fr[1].a[mt], fr[1].b[nt]);

        cp_wait1();                        // stage kt+1 resident
        __syncthreads();                   // single barrier per iteration
    }

    // ---- epilogue ----
    float bn0[4], bn1[4];
    if (EPI == 4) {
        #pragma unroll
        for (int nt = 0; nt < 4; nt++) {
            int col = nBase + wn * 32 + nt * 8 + tig * 2;
            bn0[nt] = bias[col]; bn1[nt] = bias[col + 1];
        }
    }
    #pragma unroll
    for (int mt = 0; mt < 4; mt++) {
        #pragma unroll
        for (int half = 0; half < 2; half++) {
            const int row = mBase + wm * 64 + mt * 16 + g + half * 8;
            float bm = (EPI == 1 || EPI == 2) ? bias[row] : 0.f;
            float rsmul = (EPI == 5) ? aux[(size_t)z * LL + row] : 0.f;
            float rsum = 0.f;
            #pragma unroll
            for (int nt = 0; nt < 4; nt++) {
                const int col = nBase + wn * 32 + nt * 8 + tig * 2;
                float v0 = acc[mt][nt][half * 2 + 0];
                float v1 = acc[mt][nt][half * 2 + 1];
                if (EPI == 1 || EPI == 2) { v0 += bm; v1 += bm; }
                if (EPI == 4) { v0 += bn0[nt]; v1 += bn1[nt]; }
                if (EPI == 5) { v0 *= rsmul; v1 *= rsmul; }
                if (EPI == 2) {
                    const float* xr = X + strX * z + (size_t)row * ldo + col;
                    v0 += xr[0]; v1 += xr[1];
                }
                if (EPI == 3) {
                    v0 = __expf(v0 * scale);
                    v1 = __expf(v1 * scale);
                    __nv_bfloat162 st = __floats2bfloat162_rn(v0, v1);
                    *(__nv_bfloat162*)((__nv_bfloat16*)Og + strO * z
                                       + (size_t)row * ldo + col) = st;
                    rsum += __bfloat162float(st.x) + __bfloat162float(st.y);
                } else if constexpr (OUT_BF16) {
                    __nv_bfloat162 st = __floats2bfloat162_rn(v0, v1);
                    *(__nv_bfloat162*)((__nv_bfloat16*)Og + strO * z
                                       + (size_t)row * ldo + col) = st;
                } else {
                    float2 st = { v0, v1 };
                    *(float2*)((float*)Og + strO * z + (size_t)row * ldo + col) = st;
                }
            }
            if (EPI == 3) {
                rsum += __shfl_xor_sync(0xffffffffu, rsum, 1);
                rsum += __shfl_xor_sync(0xffffffffu, rsum, 2);
                if (tig == 0)
                    aux[((size_t)z * LL + row) * 64 + blockIdx.x * 4 + wn] = rsum;
            }
        }
    }
}

// ---------------------------------------------------------------------------
// Rowsum reduce: 64 partials per row -> 1/rowsum
// ---------------------------------------------------------------------------
__global__ __launch_bounds__(256)
void rs_reduce(const float* __restrict__ part, float* __restrict__ invrs) {
    const int row = blockIdx.x * 8 + (threadIdx.x >> 5);
    const int lane = threadIdx.x & 31;
    const float* p = part + (size_t)row * 64;
    float s = p[lane] + p[lane + 32];
    s = warp_sum(s);
    if (lane == 0) invrs[row] = 1.0f / s;
}

// ---------------------------------------------------------------------------
// Launch
// ---------------------------------------------------------------------------
extern "C" void kernel_launch(void* const* d_in, const int* in_sizes, int n_in,
                              void* d_out, int out_size) {
    const float* x        = (const float*)d_in[0];
    const float* gn_gamma = (const float*)d_in[1];
    const float* gn_beta  = (const float*)d_in[2];
    const float* Wq = (const float*)d_in[3];
    const float* bq = (const float*)d_in[4];
    const float* Wk = (const float*)d_in[5];
    const float* bk = (const float*)d_in[6];
    const float* Wv = (const float*)d_in[7];
    const float* bv = (const float*)d_in[8];
    const float* Wo = (const float*)d_in[9];
    const float* bo = (const float*)d_in[10];
    float* out = (float*)d_out;

    __nv_bfloat16 *hT, *qT, *kT, *v, *aT, *e;
    float *part, *invrs; float2* stats;
    cudaGetSymbolAddress((void**)&hT, g_hT);
    cudaGetSymbolAddress((void**)&qT, g_qT);
    cudaGetSymbolAddress((void**)&kT, g_kT);
    cudaGetSymbolAddress((void**)&v,  g_v);
    cudaGetSymbolAddress((void**)&aT, g_aT);
    cudaGetSymbolAddress((void**)&e,  g_e);
    cudaGetSymbolAddress((void**)&part, g_part);
    cudaGetSymbolAddress((void**)&invrs, g_invrs);
    cudaGetSymbolAddress((void**)&stats, g_stats);

    const size_t CL  = (size_t)CC * LL;
    const size_t LLs = (size_t)LL * LL;
    const float scale = 0.044194173824159216f;   // 1/sqrt(512)

    cudaFuncSetAttribute(gemm_cp<4, false, true,  true>,
                         cudaFuncAttributeMaxDynamicSharedMemorySize, SM_TOTAL);
    cudaFuncSetAttribute(gemm_cp<1, true,  false, true>,
                         cudaFuncAttributeMaxDynamicSharedMemorySize, SM_TOTAL);
    cudaFuncSetAttribute(gemm_cp<3, false, false, true>,
                         cudaFuncAttributeMaxDynamicSharedMemorySize, SM_TOTAL);
    cudaFuncSetAttribute(gemm_cp<5, false, false, true>,
                         cudaFuncAttributeMaxDynamicSharedMemorySize, SM_TOTAL);
    cudaFuncSetAttribute(gemm_cp<2, true,  false, false>,
                         cudaFuncAttributeMaxDynamicSharedMemorySize, SM_TOTAL);

    // 1. GroupNorm
    gn_stats<<<BATCH * NGROUPS, 512>>>(x, stats);
    gn_norm_t<<<dim3(LL / 32, CC / 64, BATCH), 256>>>(x, stats, gn_gamma, gn_beta, hT);

    // 2. qT[l][o] = hT @ Wq^T + bq   (M=L, N=C, K=C)
    dim3 gT(CC / 128, LL / 128, BATCH);
    gemm_cp<4, false, true, true><<<gT, 256, SM_TOTAL>>>(
        hT, CC, CL, Wq, CC, 0, qT, CC, CL, CC, bq, nullptr, 0, 0.f, nullptr);
    gemm_cp<4, false, true, true><<<gT, 256, SM_TOTAL>>>(
        hT, CC, CL, Wk, CC, 0, kT, CC, CL, CC, bk, nullptr, 0, 0.f, nullptr);
    //    v[c][l] = Wv @ h + bv   (M=C, N=L, K=C)
    dim3 gV(LL / 128, CC / 128, BATCH);
    gemm_cp<1, true, false, true><<<gV, 256, SM_TOTAL>>>(
        Wv, CC, 0, hT, CC, CL, v, LL, CL, CC, bv, nullptr, 0, 0.f, nullptr);

    // 3. e[i][j] = exp(scale * qT@kT^T), + rowsum partials  (M=N=L, K=C)
    dim3 gS(LL / 128, LL / 128, BATCH);
    gemm_cp<3, false, false, true><<<gS, 256, SM_TOTAL>>>(
        qT, CC, CL, kT, CC, CL, e, LL, LLs, CC, nullptr, nullptr, 0, scale, part);

    // 4. 1/rowsum
    rs_reduce<<<BATCH * LL / 8, 256>>>(part, invrs);

    // 5. aT[i][c] = (e @ v^T) * invrs[i]   (M=L, N=C, K=L)
    gemm_cp<5, false, false, true><<<gT, 256, SM_TOTAL>>>(
        e, LL, LLs, v, LL, CL, aT, CC, CL, LL, nullptr, nullptr, 0, 0.f, invrs);

    // 6. out[o][l] = x + Wo @ aT^T + bo   (M=C, N=L, K=C)
    gemm_cp<2, true, false, false><<<gV, 256, SM_TOTAL>>>(
        Wo, CC, 0, aT, CC, CL, out, LL, CL, CC, bo, x, CL, 0.f, nullptr);
}

// round 9
// speedup vs baseline: 2.1537x; 1.0623x over previous
#include <cuda_runtime.h>
#include <cuda_bf16.h>
#include <cstdint>
#include <cstddef>

#define BATCH 8
#define CC    512
#define LL    2048
#define NGROUPS 32
#define CPG   (CC / NGROUPS)
#define GROUP_ELEMS (CPG * LL)
#define EPS   1e-5f

// ---------------------------------------------------------------------------
// Device scratch (all GEMM operands k-contiguous)
// ---------------------------------------------------------------------------
__device__ __nv_bfloat16 g_hT[(size_t)BATCH * LL * CC];   // [b][l][c]
__device__ __nv_bfloat16 g_qT[(size_t)BATCH * LL * CC];   // [b][l][c]
__device__ __nv_bfloat16 g_kT[(size_t)BATCH * LL * CC];   // [b][l][c]
__device__ __nv_bfloat16 g_v [(size_t)BATCH * CC * LL];   // [b][c][l]
__device__ __nv_bfloat16 g_aT[(size_t)BATCH * LL * CC];   // [b][l][c]
__device__ __nv_bfloat16 g_e [(size_t)BATCH * LL * LL];   // exp(scores) bf16
__device__ float         g_part[(size_t)BATCH * LL * 32]; // rowsum partials
__device__ float         g_invrs[(size_t)BATCH * LL];     // 1/rowsum
__device__ float2        g_stats[BATCH * NGROUPS];

// ---------------------------------------------------------------------------
// Helpers
// ---------------------------------------------------------------------------
__device__ __forceinline__ float warp_sum(float v) {
    #pragma unroll
    for (int o = 16; o > 0; o >>= 1) v += __shfl_xor_sync(0xffffffffu, v, o);
    return v;
}
__device__ __forceinline__ void ldsm4(uint32_t* r, const void* p) {
    uint32_t a = (uint32_t)__cvta_generic_to_shared(p);
    asm volatile("ldmatrix.sync.aligned.m8n8.x4.shared.b16 {%0,%1,%2,%3}, [%4];"
                 : "=r"(r[0]), "=r"(r[1]), "=r"(r[2]), "=r"(r[3]) : "r"(a));
}
__device__ __forceinline__ void mma16(float* d, const uint32_t* a, const uint32_t* b) {
    asm volatile(
        "mma.sync.aligned.m16n8k16.row.col.f32.bf16.bf16.f32 "
        "{%0,%1,%2,%3}, {%4,%5,%6,%7}, {%8,%9}, {%0,%1,%2,%3};\n"
        : "+f"(d[0]), "+f"(d[1]), "+f"(d[2]), "+f"(d[3])
        : "r"(a[0]), "r"(a[1]), "r"(a[2]), "r"(a[3]), "r"(b[0]), "r"(b[1]));
}
__device__ __forceinline__ uint32_t packbf2(float x, float y) {
    __nv_bfloat162 t = __floats2bfloat162_rn(x, y);
    return *(uint32_t*)&t;
}
__device__ __forceinline__ uint4 pack8(float4 a, float4 b) {
    uint4 r;
    r.x = packbf2(a.x, a.y); r.y = packbf2(a.z, a.w);
    r.z = packbf2(b.x, b.y); r.w = packbf2(b.z, b.w);
    return r;
}
__device__ __forceinline__ void cp16(void* smem_dst, const void* gmem_src) {
    uint32_t d = (uint32_t)__cvta_generic_to_shared(smem_dst);
    asm volatile("cp.async.cg.shared.global [%0], [%1], 16;" :: "r"(d), "l"(gmem_src));
}
__device__ __forceinline__ void cp_commit() {
    asm volatile("cp.async.commit_group;" ::: "memory");
}
__device__ __forceinline__ void cp_wait1() {
    asm volatile("cp.async.wait_group 1;" ::: "memory");
}

// ---------------------------------------------------------------------------
// GroupNorm pass 1 (stats)
// ---------------------------------------------------------------------------
__global__ void gn_stats(const float* __restrict__ x, float2* __restrict__ stats) {
    const int bg = blockIdx.x;
    const int b  = bg / NGROUPS;
    const int g  = bg % NGROUPS;
    const size_t base = ((size_t)b * CC + (size_t)g * CPG) * LL;
    const float* xp = x + base;

    float s = 0.f, s2 = 0.f;
    for (int i = threadIdx.x; i < GROUP_ELEMS; i += blockDim.x) {
        float v = xp[i];
        s += v; s2 += v * v;
    }
    __shared__ float red1[16], red2[16];
    s = warp_sum(s); s2 = warp_sum(s2);
    const int lane = threadIdx.x & 31, wid = threadIdx.x >> 5;
    if (lane == 0) { red1[wid] = s; red2[wid] = s2; }
    __syncthreads();
    if (threadIdx.x == 0) {
        float t = 0.f, t2 = 0.f;
        #pragma unroll
        for (int i = 0; i < 16; i++) { t += red1[i]; t2 += red2[i]; }
        float mean = t * (1.0f / GROUP_ELEMS);
        float var  = t2 * (1.0f / GROUP_ELEMS) - mean * mean;
        stats[bg] = make_float2(mean, rsqrtf(var + EPS));
    }
}

// ---------------------------------------------------------------------------
// GroupNorm pass 2: normalize + transpose + bf16 -> hT[b][l][c]
// ---------------------------------------------------------------------------
__global__ void gn_norm_t(const float* __restrict__ x,
                          const float2* __restrict__ stats,
                          const float* __restrict__ gamma,
                          const float* __restrict__ beta,
                          __nv_bfloat16* __restrict__ hT) {
    const int b = blockIdx.z;
    const int l0 = blockIdx.x * 32;
    const int c0 = blockIdx.y * 64;
    const int tx = threadIdx.x & 31, ty = threadIdx.x >> 5;
    __shared__ float tile[64][33];

    const float* xb = x + (size_t)b * CC * LL;
    #pragma unroll
    for (int i = 0; i < 8; i++) {
        int c = c0 + i * 8 + ty;
        float2 st = stats[b * NGROUPS + (c >> 4)];
        float gm = gamma[c], bt = beta[c];
        float xv = xb[(size_t)c * LL + l0 + tx];
        tile[c - c0][tx] = (xv - st.x) * st.y * gm + bt;
    }
    __syncthreads();
    __nv_bfloat16* ht = hT + (size_t)b * LL * CC;
    #pragma unroll
    for (int i = 0; i < 4; i++) {
        int l = i * 8 + ty;
        __nv_bfloat162 o;
        o.x = __float2bfloat16_rn(tile[tx * 2][l]);
        o.y = __float2bfloat16_rn(tile[tx * 2 + 1][l]);
        *(__nv_bfloat162*)(ht + (size_t)(l0 + l) * CC + c0 + tx * 2) = o;
    }
}

// ---------------------------------------------------------------------------
// bf16 mma.sync GEMM.  4 warps, CTA tile 128x128xBK32, warp tile 64x64.
// 3-stage cp.async.  Per ks-step: 8 LDSM.x4 feed 32 MMAs (ratio 0.25).
//   out[b,m,n] = sum_k A[m,k] * B[n,k]  (+ epilogue)
// EPI: 1 +bias[m] ; 2 +bias[m]+X, fp32 out ; 3 exp(v*scale) + rowsum partials
//      4 +bias[n] ; 5 *aux[m] (inv rowsum)
// ---------------------------------------------------------------------------
#define SROW 40        // 32 + 8 pad (80B rows: 16B aligned, ldmatrix conflict-free)
#define STG_ELEM (128 * SROW)
#define SM_TOTAL (6 * STG_ELEM * 2)   // 3 stages x (A+B), bf16 = 61440 B

template<int EPI, bool A_F32, bool B_F32, bool OUT_BF16>
__global__ __launch_bounds__(128, 2)
void gemm_cp(const void* __restrict__ Ag, int lda, size_t strA,
             const void* __restrict__ Bg, int ldb, size_t strB,
             void* __restrict__ Og, int ldo, size_t strO,
             int K, const float* __restrict__ bias,
             const float* __restrict__ X, size_t strX,
             float scale, float* __restrict__ aux) {
    extern __shared__ __align__(16) __nv_bfloat16 smem[];
    __nv_bfloat16* smA = smem;                 // 3 stages
    __nv_bfloat16* smB = smem + 3 * STG_ELEM;  // 3 stages

    const int tid = threadIdx.x, lane = tid & 31, warp = tid >> 5;   // warp 0..3
    const int wm = warp >> 1, wn = warp & 1;                          // 2x2
    const int g = lane >> 2, tig = lane & 3;
    const int mBase = blockIdx.y * 128, nBase = blockIdx.x * 128;
    const int z = blockIdx.z;

    const int nk = K >> 5;

    auto issue_stage = [&](int kt) {
        if (kt < nk) {
            const int buf = kt % 3;
            const int k0 = kt << 5;
            __nv_bfloat16* sA = smA + buf * STG_ELEM;
            __nv_bfloat16* sB = smB + buf * STG_ELEM;
            #pragma unroll
            for (int it = 0; it < 4; it++) {
                const int s = tid + it * 128;
                const int row = s >> 2;
                const int col8 = (s & 3) * 8;
                if constexpr (A_F32) {
                    const float* p = (const float*)Ag + strA * z
                                   + (size_t)(mBase + row) * lda + k0 + col8;
                    *(uint4*)(sA + row * SROW + col8) =
                        pack8(*(const float4*)p, *(const float4*)(p + 4));
                } else {
                    const __nv_bfloat16* p = (const __nv_bfloat16*)Ag + strA * z
                                           + (size_t)(mBase + row) * lda + k0 + col8;
                    cp16(sA + row * SROW + col8, p);
                }
                if constexpr (B_F32) {
                    const float* p = (const float*)Bg + strB * z
                                   + (size_t)(nBase + row) * ldb + k0 + col8;
                    *(uint4*)(sB + row * SROW + col8) =
                        pack8(*(const float4*)p, *(const float4*)(p + 4));
                } else {
                    const __nv_bfloat16* p = (const __nv_bfloat16*)Bg + strB * z
                                           + (size_t)(nBase + row) * ldb + k0 + col8;
                    cp16(sB + row * SROW + col8, p);
                }
            }
        }
        cp_commit();
    };

    float acc[4][8][4];
    #pragma unroll
    for (int i = 0; i < 4; i++)
        #pragma unroll
        for (int j = 0; j < 8; j++)
            #pragma unroll
            for (int r = 0; r < 4; r++) acc[i][j][r] = 0.f;

    issue_stage(0);
    issue_stage(1);
    cp_wait1();            // stage 0 resident
    __syncthreads();

    for (int kt = 0; kt < nk; kt++) {
        const int buf = kt % 3;
        const __nv_bfloat16* sA = smA + buf * STG_ELEM;
        const __nv_bfloat16* sB = smB + buf * STG_ELEM;

        issue_stage(kt + 2);   // fill (kt-1)%3 — its readers passed last barrier

        #pragma unroll
        for (int ks = 0; ks < 2; ks++) {
            uint32_t af[4][4], bf[8][2];
            // 8 LDSM.x4, batched back-to-back
            #pragma unroll
            for (int mt = 0; mt < 4; mt++) {
                const __nv_bfloat16* p = &sA[(wm * 64 + mt * 16 + (lane & 15)) * SROW
                                             + ks * 16 + ((lane >> 4) << 3)];
                ldsm4(af[mt], p);
            }
            #pragma unroll
            for (int np = 0; np < 4; np++) {
                const __nv_bfloat16* p = &sB[(wn * 64 + np * 16 + (lane & 7) + ((lane >> 4) << 3)) * SROW
                                             + ks * 16 + (((lane >> 3) & 1) << 3)];
                uint32_t t[4];
                ldsm4(t, p);
                bf[np * 2][0] = t[0]; bf[np * 2][1] = t[1];
                bf[np * 2 + 1][0] = t[2]; bf[np * 2 + 1][1] = t[3];
            }
            // 32 MMAs
            #pragma unroll
            for (int mt = 0; mt < 4; mt++)
                #pragma unroll
                for (int nt = 0; nt < 8; nt++)
                    mma16(acc[mt][nt], af[mt], bf[nt]);
        }

        cp_wait1();            // stage kt+1 resident
        __syncthreads();       // one barrier per k-tile
    }

    // ---- epilogue ----
    float bn0[8], bn1[8];
    if (EPI == 4) {
        #pragma unroll
        for (int nt = 0; nt < 8; nt++) {
            int col = nBase + wn * 64 + nt * 8 + tig * 2;
            bn0[nt] = bias[col]; bn1[nt] = bias[col + 1];
        }
    }
    #pragma unroll
    for (int mt = 0; mt < 4; mt++) {
        #pragma unroll
        for (int half = 0; half < 2; half++) {
            const int row = mBase + wm * 64 + mt * 16 + g + half * 8;
            float bm = (EPI == 1 || EPI == 2) ? bias[row] : 0.f;
            float rsmul = (EPI == 5) ? aux[(size_t)z * LL + row] : 0.f;
            float rsum = 0.f;
            #pragma unroll
            for (int nt = 0; nt < 8; nt++) {
                const int col = nBase + wn * 64 + nt * 8 + tig * 2;
                float v0 = acc[mt][nt][half * 2 + 0];
                float v1 = acc[mt][nt][half * 2 + 1];
                if (EPI == 1 || EPI == 2) { v0 += bm; v1 += bm; }
                if (EPI == 4) { v0 += bn0[nt]; v1 += bn1[nt]; }
                if (EPI == 5) { v0 *= rsmul; v1 *= rsmul; }
                if (EPI == 2) {
                    const float* xr = X + strX * z + (size_t)row * ldo + col;
                    v0 += xr[0]; v1 += xr[1];
                }
                if (EPI == 3) {
                    v0 = __expf(v0 * scale);
                    v1 = __expf(v1 * scale);
                    __nv_bfloat162 st = __floats2bfloat162_rn(v0, v1);
                    *(__nv_bfloat162*)((__nv_bfloat16*)Og + strO * z
                                       + (size_t)row * ldo + col) = st;
                    rsum += __bfloat162float(st.x) + __bfloat162float(st.y);
                } else if constexpr (OUT_BF16) {
                    __nv_bfloat162 st = __floats2bfloat162_rn(v0, v1);
                    *(__nv_bfloat162*)((__nv_bfloat16*)Og + strO * z
                                       + (size_t)row * ldo + col) = st;
                } else {
                    float2 st = { v0, v1 };
                    *(float2*)((float*)Og + strO * z + (size_t)row * ldo + col) = st;
                }
            }
            if (EPI == 3) {
                rsum += __shfl_xor_sync(0xffffffffu, rsum, 1);
                rsum += __shfl_xor_sync(0xffffffffu, rsum, 2);
                if (tig == 0)
                    aux[((size_t)z * LL + row) * 32 + blockIdx.x * 2 + wn] = rsum;
            }
        }
    }
}

// ---------------------------------------------------------------------------
// Rowsum reduce: 32 partials per row -> 1/rowsum
// ---------------------------------------------------------------------------
__global__ __launch_bounds__(256)
void rs_reduce(const float* __restrict__ part, float* __restrict__ invrs) {
    const int row = blockIdx.x * 8 + (threadIdx.x >> 5);
    const int lane = threadIdx.x & 31;
    float s = part[(size_t)row * 32 + lane];
    s = warp_sum(s);
    if (lane == 0) invrs[row] = 1.0f / s;
}

// ---------------------------------------------------------------------------
// Launch
// ---------------------------------------------------------------------------
extern "C" void kernel_launch(void* const* d_in, const int* in_sizes, int n_in,
                              void* d_out, int out_size) {
    const float* x        = (const float*)d_in[0];
    const float* gn_gamma = (const float*)d_in[1];
    const float* gn_beta  = (const float*)d_in[2];
    const float* Wq = (const float*)d_in[3];
    const float* bq = (const float*)d_in[4];
    const float* Wk = (const float*)d_in[5];
    const float* bk = (const float*)d_in[6];
    const float* Wv = (const float*)d_in[7];
    const float* bv = (const float*)d_in[8];
    const float* Wo = (const float*)d_in[9];
    const float* bo = (const float*)d_in[10];
    float* out = (float*)d_out;

    __nv_bfloat16 *hT, *qT, *kT, *v, *aT, *e;
    float *part, *invrs; float2* stats;
    cudaGetSymbolAddress((void**)&hT, g_hT);
    cudaGetSymbolAddress((void**)&qT, g_qT);
    cudaGetSymbolAddress((void**)&kT, g_kT);
    cudaGetSymbolAddress((void**)&v,  g_v);
    cudaGetSymbolAddress((void**)&aT, g_aT);
    cudaGetSymbolAddress((void**)&e,  g_e);
    cudaGetSymbolAddress((void**)&part, g_part);
    cudaGetSymbolAddress((void**)&invrs, g_invrs);
    cudaGetSymbolAddress((void**)&stats, g_stats);

    const size_t CL  = (size_t)CC * LL;
    const size_t LLs = (size_t)LL * LL;
    const float scale = 0.044194173824159216f;   // 1/sqrt(512)

    cudaFuncSetAttribute(gemm_cp<4, false, true,  true>,
                         cudaFuncAttributeMaxDynamicSharedMemorySize, SM_TOTAL);
    cudaFuncSetAttribute(gemm_cp<1, true,  false, true>,
                         cudaFuncAttributeMaxDynamicSharedMemorySize, SM_TOTAL);
    cudaFuncSetAttribute(gemm_cp<3, false, false, true>,
                         cudaFuncAttributeMaxDynamicSharedMemorySize, SM_TOTAL);
    cudaFuncSetAttribute(gemm_cp<5, false, false, true>,
                         cudaFuncAttributeMaxDynamicSharedMemorySize, SM_TOTAL);
    cudaFuncSetAttribute(gemm_cp<2, true,  false, false>,
                         cudaFuncAttributeMaxDynamicSharedMemorySize, SM_TOTAL);

    // 1. GroupNorm
    gn_stats<<<BATCH * NGROUPS, 512>>>(x, stats);
    gn_norm_t<<<dim3(LL / 32, CC / 64, BATCH), 256>>>(x, stats, gn_gamma, gn_beta, hT);

    // 2. qT[l][o] = hT @ Wq^T + bq   (M=L, N=C, K=C)
    dim3 gT(CC / 128, LL / 128, BATCH);
    gemm_cp<4, false, true, true><<<gT, 128, SM_TOTAL>>>(
        hT, CC, CL, Wq, CC, 0, qT, CC, CL, CC, bq, nullptr, 0, 0.f, nullptr);
    gemm_cp<4, false, true, true><<<gT, 128, SM_TOTAL>>>(
        hT, CC, CL, Wk, CC, 0, kT, CC, CL, CC, bk, nullptr, 0, 0.f, nullptr);
    //    v[c][l] = Wv @ h + bv   (M=C, N=L, K=C)
    dim3 gV(LL / 128, CC / 128, BATCH);
    gemm_cp<1, true, false, true><<<gV, 128, SM_TOTAL>>>(
        Wv, CC, 0, hT, CC, CL, v, LL, CL, CC, bv, nullptr, 0, 0.f, nullptr);

    // 3. e[i][j] = exp(scale * qT@kT^T), + rowsum partials  (M=N=L, K=C)
    dim3 gS(LL / 128, LL / 128, BATCH);
    gemm_cp<3, false, false, true><<<gS, 128, SM_TOTAL>>>(
        qT, CC, CL, kT, CC, CL, e, LL, LLs, CC, nullptr, nullptr, 0, scale, part);

    // 4. 1/rowsum
    rs_reduce<<<BATCH * LL / 8, 256>>>(part, invrs);

    // 5. aT[i][c] = (e @ v^T) * invrs[i]   (M=L, N=C, K=L)
    gemm_cp<5, false, false, true><<<gT, 128, SM_TOTAL>>>(
        e, LL, LLs, v, LL, CL, aT, CC, CL, LL, nullptr, nullptr, 0, 0.f, invrs);

    // 6. out[o][l] = x + Wo @ aT^T + bo   (M=C, N=L, K=C)
    gemm_cp<2, true, false, false><<<gV, 128, SM_TOTAL>>>(
        Wo, CC, 0, aT, CC, CL, out, LL, CL, CC, bo, x, CL, 0.f, nullptr);
}

// round 10
// speedup vs baseline: 2.2422x; 1.0411x over previous
#include <cuda_runtime.h>
#include <cuda_bf16.h>
#include <cstdint>
#include <cstddef>

#define BATCH 8
#define CC    512
#define LL    2048
#define NGROUPS 32
#define CPG   (CC / NGROUPS)
#define GROUP_ELEMS (CPG * LL)
#define EPS   1e-5f

// ---------------------------------------------------------------------------
// Device scratch (all GEMM operands k-contiguous)
// ---------------------------------------------------------------------------
__device__ __nv_bfloat16 g_hT[(size_t)BATCH * LL * CC];   // [b][l][c]
__device__ __nv_bfloat16 g_qT[(size_t)BATCH * LL * CC];   // [b][l][c]
__device__ __nv_bfloat16 g_kT[(size_t)BATCH * LL * CC];   // [b][l][c]
__device__ __nv_bfloat16 g_v [(size_t)BATCH * CC * LL];   // [b][c][l]
__device__ __nv_bfloat16 g_aT[(size_t)BATCH * LL * CC];   // [b][l][c]
__device__ __nv_bfloat16 g_e [(size_t)BATCH * LL * LL];   // exp(scores) bf16
__device__ float         g_part[(size_t)BATCH * LL * 32]; // rowsum partials
__device__ float         g_invrs[(size_t)BATCH * LL];     // 1/rowsum
__device__ float2        g_stats[BATCH * NGROUPS];

// ---------------------------------------------------------------------------
// Helpers
// ---------------------------------------------------------------------------
__device__ __forceinline__ float warp_sum(float v) {
    #pragma unroll
    for (int o = 16; o > 0; o >>= 1) v += __shfl_xor_sync(0xffffffffu, v, o);
    return v;
}
__device__ __forceinline__ void ldsm4(uint32_t* r, const void* p) {
    uint32_t a = (uint32_t)__cvta_generic_to_shared(p);
    asm volatile("ldmatrix.sync.aligned.m8n8.x4.shared.b16 {%0,%1,%2,%3}, [%4];"
                 : "=r"(r[0]), "=r"(r[1]), "=r"(r[2]), "=r"(r[3]) : "r"(a));
}
__device__ __forceinline__ void mma16(float* d, const uint32_t* a, const uint32_t* b) {
    asm volatile(
        "mma.sync.aligned.m16n8k16.row.col.f32.bf16.bf16.f32 "
        "{%0,%1,%2,%3}, {%4,%5,%6,%7}, {%8,%9}, {%0,%1,%2,%3};\n"
        : "+f"(d[0]), "+f"(d[1]), "+f"(d[2]), "+f"(d[3])
        : "r"(a[0]), "r"(a[1]), "r"(a[2]), "r"(a[3]), "r"(b[0]), "r"(b[1]));
}
__device__ __forceinline__ uint32_t packbf2(float x, float y) {
    __nv_bfloat162 t = __floats2bfloat162_rn(x, y);
    return *(uint32_t*)&t;
}
__device__ __forceinline__ uint4 pack8(float4 a, float4 b) {
    uint4 r;
    r.x = packbf2(a.x, a.y); r.y = packbf2(a.z, a.w);
    r.z = packbf2(b.x, b.y); r.w = packbf2(b.z, b.w);
    return r;
}
__device__ __forceinline__ void cp16(void* smem_dst, const void* gmem_src) {
    uint32_t d = (uint32_t)__cvta_generic_to_shared(smem_dst);
    asm volatile("cp.async.cg.shared.global [%0], [%1], 16;" :: "r"(d), "l"(gmem_src));
}
__device__ __forceinline__ void cp_commit() {
    asm volatile("cp.async.commit_group;" ::: "memory");
}
__device__ __forceinline__ void cp_wait1() {
    asm volatile("cp.async.wait_group 1;" ::: "memory");
}

// ---------------------------------------------------------------------------
// GroupNorm pass 1 (stats)
// ---------------------------------------------------------------------------
__global__ void gn_stats(const float* __restrict__ x, float2* __restrict__ stats) {
    const int bg = blockIdx.x;
    const int b  = bg / NGROUPS;
    const int g  = bg % NGROUPS;
    const size_t base = ((size_t)b * CC + (size_t)g * CPG) * LL;
    const float* xp = x + base;

    float s = 0.f, s2 = 0.f;
    for (int i = threadIdx.x; i < GROUP_ELEMS; i += blockDim.x) {
        float v = xp[i];
        s += v; s2 += v * v;
    }
    __shared__ float red1[16], red2[16];
    s = warp_sum(s); s2 = warp_sum(s2);
    const int lane = threadIdx.x & 31, wid = threadIdx.x >> 5;
    if (lane == 0) { red1[wid] = s; red2[wid] = s2; }
    __syncthreads();
    if (threadIdx.x == 0) {
        float t = 0.f, t2 = 0.f;
        #pragma unroll
        for (int i = 0; i < 16; i++) { t += red1[i]; t2 += red2[i]; }
        float mean = t * (1.0f / GROUP_ELEMS);
        float var  = t2 * (1.0f / GROUP_ELEMS) - mean * mean;
        stats[bg] = make_float2(mean, rsqrtf(var + EPS));
    }
}

// ---------------------------------------------------------------------------
// GroupNorm pass 2: normalize + transpose + bf16 -> hT[b][l][c]
// ---------------------------------------------------------------------------
__global__ void gn_norm_t(const float* __restrict__ x,
                          const float2* __restrict__ stats,
                          const float* __restrict__ gamma,
                          const float* __restrict__ beta,
                          __nv_bfloat16* __restrict__ hT) {
    const int b = blockIdx.z;
    const int l0 = blockIdx.x * 32;
    const int c0 = blockIdx.y * 64;
    const int tx = threadIdx.x & 31, ty = threadIdx.x >> 5;
    __shared__ float tile[64][33];

    const float* xb = x + (size_t)b * CC * LL;
    #pragma unroll
    for (int i = 0; i < 8; i++) {
        int c = c0 + i * 8 + ty;
        float2 st = stats[b * NGROUPS + (c >> 4)];
        float gm = gamma[c], bt = beta[c];
        float xv = xb[(size_t)c * LL + l0 + tx];
        tile[c - c0][tx] = (xv - st.x) * st.y * gm + bt;
    }
    __syncthreads();
    __nv_bfloat16* ht = hT + (size_t)b * LL * CC;
    #pragma unroll
    for (int i = 0; i < 4; i++) {
        int l = i * 8 + ty;
        __nv_bfloat162 o;
        o.x = __float2bfloat16_rn(tile[tx * 2][l]);
        o.y = __float2bfloat16_rn(tile[tx * 2 + 1][l]);
        *(__nv_bfloat162*)(ht + (size_t)(l0 + l) * CC + c0 + tx * 2) = o;
    }
}

// ---------------------------------------------------------------------------
// bf16 mma.sync GEMM.  4 warps, CTA tile 128x128 x BK=64, warp tile 64x64.
// 2-stage cp.async, 128 MMAs per k-tile between sync points.
//   out[b,m,n] = sum_k A[m,k] * B[n,k]  (+ epilogue)
// EPI: 1 +bias[m] ; 2 +bias[m]+X, fp32 out ; 3 exp(v*scale) + rowsum partials
//      4 +bias[n] ; 5 *aux[m] (inv rowsum)
// Optional merged mode: if Bg2 != nullptr, blocks with z >= gridDim.z/2 use
// (Bg2, Og2, bias2) and batch index z - gridDim.z/2  (q & k fused launch).
// ---------------------------------------------------------------------------
#define BKK 64
#define SROW 72        // 64 + 8 pad (144B rows: 16B aligned, ldmatrix conflict-free)
#define STG_ELEM (128 * SROW)
#define SM_TOTAL (4 * STG_ELEM * 2)   // 2 stages x (A+B) bf16 = 73728 B

template<int EPI, bool A_F32, bool B_F32, bool OUT_BF16>
__global__ __launch_bounds__(128, 2)
void gemm_cp(const void* __restrict__ Ag, int lda, size_t strA,
             const void* __restrict__ Bg, int ldb, size_t strB,
             void* __restrict__ Og, int ldo, size_t strO,
             int K, const float* __restrict__ bias,
             const float* __restrict__ X, size_t strX,
             float scale, float* __restrict__ aux,
             const void* __restrict__ Bg2, void* __restrict__ Og2,
             const float* __restrict__ bias2) {
    extern __shared__ __align__(16) __nv_bfloat16 smem[];
    __nv_bfloat16* smA = smem;                 // 2 stages
    __nv_bfloat16* smB = smem + 2 * STG_ELEM;  // 2 stages

    const int tid = threadIdx.x, lane = tid & 31, warp = tid >> 5;   // warp 0..3
    const int wm = warp >> 1, wn = warp & 1;                          // 2x2
    const int g = lane >> 2, tig = lane & 3;
    const int mBase = blockIdx.y * 128, nBase = blockIdx.x * 128;

    // merged q/k dispatch
    int zz = blockIdx.z;
    const void* Bu = Bg; void* Ou = Og; const float* biasu = bias;
    if (Bg2 != nullptr) {
        const int half = (int)(gridDim.z >> 1);
        if (zz >= half) { Bu = Bg2; Ou = Og2; biasu = bias2; zz -= half; }
    }
    const int z = zz;

    const int nk = K / BKK;

    auto issue_stage = [&](int kt) {
        if (kt < nk) {
            const int buf = kt & 1;
            const int k0 = kt * BKK;
            __nv_bfloat16* sA = smA + buf * STG_ELEM;
            __nv_bfloat16* sB = smB + buf * STG_ELEM;
            #pragma unroll
            for (int it = 0; it < 8; it++) {
                const int s = tid + it * 128;
                const int row = s >> 3;
                const int col8 = (s & 7) * 8;
                if constexpr (A_F32) {
                    const float* p = (const float*)Ag + strA * z
                                   + (size_t)(mBase + row) * lda + k0 + col8;
                    *(uint4*)(sA + row * SROW + col8) =
                        pack8(*(const float4*)p, *(const float4*)(p + 4));
                } else {
                    const __nv_bfloat16* p = (const __nv_bfloat16*)Ag + strA * z
                                           + (size_t)(mBase + row) * lda + k0 + col8;
                    cp16(sA + row * SROW + col8, p);
                }
                if constexpr (B_F32) {
                    const float* p = (const float*)Bu + strB * z
                                   + (size_t)(nBase + row) * ldb + k0 + col8;
                    *(uint4*)(sB + row * SROW + col8) =
                        pack8(*(const float4*)p, *(const float4*)(p + 4));
                } else {
                    const __nv_bfloat16* p = (const __nv_bfloat16*)Bu + strB * z
                                           + (size_t)(nBase + row) * ldb + k0 + col8;
                    cp16(sB + row * SROW + col8, p);
                }
            }
        }
        cp_commit();
    };

    float acc[4][8][4];
    #pragma unroll
    for (int i = 0; i < 4; i++)
        #pragma unroll
        for (int j = 0; j < 8; j++)
            #pragma unroll
            for (int r = 0; r < 4; r++) acc[i][j][r] = 0.f;

    issue_stage(0);
    issue_stage(1);

    for (int kt = 0; kt < nk; kt++) {
        const int buf = kt & 1;
        const __nv_bfloat16* sA = smA + buf * STG_ELEM;
        const __nv_bfloat16* sB = smB + buf * STG_ELEM;

        cp_wait1();            // stage kt resident
        __syncthreads();

        #pragma unroll
        for (int ks = 0; ks < 4; ks++) {
            uint32_t af[4][4], bf[8][2];
            #pragma unroll
            for (int mt = 0; mt < 4; mt++) {
                const __nv_bfloat16* p = &sA[(wm * 64 + mt * 16 + (lane & 15)) * SROW
                                             + ks * 16 + ((lane >> 4) << 3)];
                ldsm4(af[mt], p);
            }
            #pragma unroll
            for (int np = 0; np < 4; np++) {
                const __nv_bfloat16* p = &sB[(wn * 64 + np * 16 + (lane & 7) + ((lane >> 4) << 3)) * SROW
                                             + ks * 16 + (((lane >> 3) & 1) << 3)];
                uint32_t t[4];
                ldsm4(t, p);
                bf[np * 2][0] = t[0]; bf[np * 2][1] = t[1];
                bf[np * 2 + 1][0] = t[2]; bf[np * 2 + 1][1] = t[3];
            }
            #pragma unroll
            for (int mt = 0; mt < 4; mt++)
                #pragma unroll
                for (int nt = 0; nt < 8; nt++)
                    mma16(acc[mt][nt], af[mt], bf[nt]);
        }

        __syncthreads();       // all warps finished reading buf
        issue_stage(kt + 2);   // refill it
    }

    // ---- epilogue ----
    float bn0[8], bn1[8];
    if (EPI == 4) {
        #pragma unroll
        for (int nt = 0; nt < 8; nt++) {
            int col = nBase + wn * 64 + nt * 8 + tig * 2;
            bn0[nt] = biasu[col]; bn1[nt] = biasu[col + 1];
        }
    }
    #pragma unroll
    for (int mt = 0; mt < 4; mt++) {
        #pragma unroll
        for (int half = 0; half < 2; half++) {
            const int row = mBase + wm * 64 + mt * 16 + g + half * 8;
            float bm = (EPI == 1 || EPI == 2) ? biasu[row] : 0.f;
            float rsmul = (EPI == 5) ? aux[(size_t)z * LL + row] : 0.f;
            float rsum = 0.f;
            #pragma unroll
            for (int nt = 0; nt < 8; nt++) {
                const int col = nBase + wn * 64 + nt * 8 + tig * 2;
                float v0 = acc[mt][nt][half * 2 + 0];
                float v1 = acc[mt][nt][half * 2 + 1];
                if (EPI == 1 || EPI == 2) { v0 += bm; v1 += bm; }
                if (EPI == 4) { v0 += bn0[nt]; v1 += bn1[nt]; }
                if (EPI == 5) { v0 *= rsmul; v1 *= rsmul; }
                if (EPI == 2) {
                    const float* xr = X + strX * z + (size_t)row * ldo + col;
                    v0 += xr[0]; v1 += xr[1];
                }
                if (EPI == 3) {
                    v0 = __expf(v0 * scale);
                    v1 = __expf(v1 * scale);
                    __nv_bfloat162 st = __floats2bfloat162_rn(v0, v1);
                    *(__nv_bfloat162*)((__nv_bfloat16*)Ou + strO * z
                                       + (size_t)row * ldo + col) = st;
                    rsum += __bfloat162float(st.x) + __bfloat162float(st.y);
                } else if constexpr (OUT_BF16) {
                    __nv_bfloat162 st = __floats2bfloat162_rn(v0, v1);
                    *(__nv_bfloat162*)((__nv_bfloat16*)Ou + strO * z
                                       + (size_t)row * ldo + col) = st;
                } else {
                    float2 st = { v0, v1 };
                    *(float2*)((float*)Ou + strO * z + (size_t)row * ldo + col) = st;
                }
            }
            if (EPI == 3) {
                rsum += __shfl_xor_sync(0xffffffffu, rsum, 1);
                rsum += __shfl_xor_sync(0xffffffffu, rsum, 2);
                if (tig == 0)
                    aux[((size_t)z * LL + row) * 32 + blockIdx.x * 2 + wn] = rsum;
            }
        }
    }
}

// ---------------------------------------------------------------------------
// Rowsum reduce: 32 partials per row -> 1/rowsum
// ---------------------------------------------------------------------------
__global__ __launch_bounds__(256)
void rs_reduce(const float* __restrict__ part, float* __restrict__ invrs) {
    const int row = blockIdx.x * 8 + (threadIdx.x >> 5);
    const int lane = threadIdx.x & 31;
    float s = part[(size_t)row * 32 + lane];
    s = warp_sum(s);
    if (lane == 0) invrs[row] = 1.0f / s;
}

// ---------------------------------------------------------------------------
// Launch
// ---------------------------------------------------------------------------
extern "C" void kernel_launch(void* const* d_in, const int* in_sizes, int n_in,
                              void* d_out, int out_size) {
    const float* x        = (const float*)d_in[0];
    const float* gn_gamma = (const float*)d_in[1];
    const float* gn_beta  = (const float*)d_in[2];
    const float* Wq = (const float*)d_in[3];
    const float* bq = (const float*)d_in[4];
    const float* Wk = (const float*)d_in[5];
    const float* bk = (const float*)d_in[6];
    const float* Wv = (const float*)d_in[7];
    const float* bv = (const float*)d_in[8];
    const float* Wo = (const float*)d_in[9];
    const float* bo = (const float*)d_in[10];
    float* out = (float*)d_out;

    __nv_bfloat16 *hT, *qT, *kT, *v, *aT, *e;
    float *part, *invrs; float2* stats;
    cudaGetSymbolAddress((void**)&hT, g_hT);
    cudaGetSymbolAddress((void**)&qT, g_qT);
    cudaGetSymbolAddress((void**)&kT, g_kT);
    cudaGetSymbolAddress((void**)&v,  g_v);
    cudaGetSymbolAddress((void**)&aT, g_aT);
    cudaGetSymbolAddress((void**)&e,  g_e);
    cudaGetSymbolAddress((void**)&part, g_part);
    cudaGetSymbolAddress((void**)&invrs, g_invrs);
    cudaGetSymbolAddress((void**)&stats, g_stats);

    const size_t CL  = (size_t)CC * LL;
    const size_t LLs = (size_t)LL * LL;
    const float scale = 0.044194173824159216f;   // 1/sqrt(512)

    cudaFuncSetAttribute(gemm_cp<4, false, true,  true>,
                         cudaFuncAttributeMaxDynamicSharedMemorySize, SM_TOTAL);
    cudaFuncSetAttribute(gemm_cp<1, true,  false, true>,
                         cudaFuncAttributeMaxDynamicSharedMemorySize, SM_TOTAL);
    cudaFuncSetAttribute(gemm_cp<3, false, false, true>,
                         cudaFuncAttributeMaxDynamicSharedMemorySize, SM_TOTAL);
    cudaFuncSetAttribute(gemm_cp<5, false, false, true>,
                         cudaFuncAttributeMaxDynamicSharedMemorySize, SM_TOTAL);
    cudaFuncSetAttribute(gemm_cp<2, true,  false, false>,
                         cudaFuncAttributeMaxDynamicSharedMemorySize, SM_TOTAL);

    // 1. GroupNorm
    gn_stats<<<BATCH * NGROUPS, 512>>>(x, stats);
    gn_norm_t<<<dim3(LL / 32, CC / 64, BATCH), 256>>>(x, stats, gn_gamma, gn_beta, hT);

    // 2. merged q & k:  qT/kT[l][o] = hT @ W^T + b   (M=L, N=C, K=C), z=16
    dim3 gQK(CC / 128, LL / 128, 2 * BATCH);
    gemm_cp<4, false, true, true><<<gQK, 128, SM_TOTAL>>>(
        hT, CC, CL, Wq, CC, 0, qT, CC, CL, CC, bq, nullptr, 0, 0.f, nullptr,
        Wk, kT, bk);
    //    v[c][l] = Wv @ h + bv   (M=C, N=L, K=C)
    dim3 gV(LL / 128, CC / 128, BATCH);
    gemm_cp<1, true, false, true><<<gV, 128, SM_TOTAL>>>(
        Wv, CC, 0, hT, CC, CL, v, LL, CL, CC, bv, nullptr, 0, 0.f, nullptr,
        nullptr, nullptr, nullptr);

    // 3. e[i][j] = exp(scale * qT@kT^T), + rowsum partials  (M=N=L, K=C)
    dim3 gS(LL / 128, LL / 128, BATCH);
    gemm_cp<3, false, false, true><<<gS, 128, SM_TOTAL>>>(
        qT, CC, CL, kT, CC, CL, e, LL, LLs, CC, nullptr, nullptr, 0, scale, part,
        nullptr, nullptr, nullptr);

    // 4. 1/rowsum
    rs_reduce<<<BATCH * LL / 8, 256>>>(part, invrs);

    // 5. aT[i][c] = (e @ v^T) * invrs[i]   (M=L, N=C, K=L)
    dim3 gT(CC / 128, LL / 128, BATCH);
    gemm_cp<5, false, false, true><<<gT, 128, SM_TOTAL>>>(
        e, LL, LLs, v, LL, CL, aT, CC, CL, LL, nullptr, nullptr, 0, 0.f, invrs,
        nullptr, nullptr, nullptr);

    // 6. out[o][l] = x + Wo @ aT^T + bo   (M=C, N=L, K=C)
    gemm_cp<2, true, false, false><<<gV, 128, SM_TOTAL>>>(
        Wo, CC, 0, aT, CC, CL, out, LL, CL, CC, bo, x, CL, 0.f, nullptr,
        nullptr, nullptr, nullptr);
}